// round 6
// baseline (speedup 1.0000x reference)
#include <cuda_runtime.h>
#include <cstdint>

#define NN 100000
#define EE 1600000
#define HH 128
#define GG 512
#define CC 10
#define LH 384   // L*H
#define EPSV 1e-5f
#define NBLK 98  // ceil(NN/1024)

// ---------------- device scratch (no allocations allowed) ----------------
// zero-invariants: g_cnt, g_stat are zero at entry of every call
__device__ __align__(16) float g_hW[NN * HH];     // GEMM output (dinv-scaled)
__device__ __align__(16) float g_aggA[NN * HH];   // aggregation ping
__device__ __align__(16) float g_aggB[NN * HH];   // aggregation pong
__device__ float g_dinv[NN];
__device__ int   g_cnt[NN];
__device__ int   g_off[NN + 1];
__device__ int   g_cursor[NN];
__device__ int   g_srcA[EE];
__device__ int   g_bsum[128];
__device__ float g_stat[2 * HH];       // [0:128) sum, [128:256) sumsq
__device__ float g_meanL[3 * HH];      // per-layer BN stats
__device__ float g_istdL[3 * HH];
__device__ int   g_goff[GG + 1];
__device__ float g_pool[GG * LH];
__device__ float g_z[GG * HH];
__device__ float g_m2[HH];
__device__ float g_i2[HH];

// ---------------- setup kernels ----------------
__global__ void k_count(const int* __restrict__ dst) {
    int e = blockIdx.x * blockDim.x + threadIdx.x;
    if (e < EE) atomicAdd(&g_cnt[dst[e]], 1);
}

// block-local exclusive scan + block sums; also writes dinv
__global__ void s_partial() {
    __shared__ int wsum[32];
    int tid = threadIdx.x, lane = tid & 31, wid = tid >> 5;
    int idx = blockIdx.x * 1024 + tid;
    int v = (idx < NN) ? g_cnt[idx] : 0;
    if (idx < NN) g_dinv[idx] = rsqrtf((float)(v + 1));
    int x = v;
    #pragma unroll
    for (int o = 1; o < 32; o <<= 1) {
        int y = __shfl_up_sync(0xffffffffu, x, o);
        if (lane >= o) x += y;
    }
    if (lane == 31) wsum[wid] = x;
    __syncthreads();
    if (wid == 0) {
        int w = wsum[lane];
        int xx = w;
        #pragma unroll
        for (int o = 1; o < 32; o <<= 1) {
            int y = __shfl_up_sync(0xffffffffu, xx, o);
            if (lane >= o) xx += y;
        }
        wsum[lane] = xx - w;
    }
    __syncthreads();
    int incl = x + wsum[wid];
    if (idx < NN) g_off[idx] = incl - v;     // block-local exclusive
    if (tid == 1023) g_bsum[blockIdx.x] = incl;
}

// finalize offsets (block prefix scanned redundantly per block), init cursor,
// zero g_cnt, and compute per-graph offsets from sorted batch (boundary scan)
__global__ void s_add(const int* __restrict__ batch) {
    __shared__ int sb[128];
    int tid = threadIdx.x;
    if (tid < 128) sb[tid] = (tid < NBLK) ? g_bsum[tid] : 0;
    __syncthreads();
    #pragma unroll
    for (int o = 1; o < 128; o <<= 1) {
        int v = 0;
        if (tid < 128 && tid >= o) v = sb[tid - o];
        __syncthreads();
        if (tid < 128) sb[tid] += v;
        __syncthreads();
    }
    int bpre = (blockIdx.x > 0) ? sb[blockIdx.x - 1] : 0;
    int idx = blockIdx.x * 1024 + tid;
    if (idx < NN) {
        int off = g_off[idx] + bpre;
        g_off[idx] = off;
        g_cursor[idx] = off;
        g_cnt[idx] = 0;                      // restore zero-invariant
        // graph offsets: batch sorted ascending
        int b = batch[idx];
        int prev = (idx > 0) ? batch[idx - 1] : -1;
        for (int g = prev + 1; g <= b; g++) g_goff[g] = idx;
        if (idx == NN - 1)
            for (int g = b + 1; g <= GG; g++) g_goff[g] = NN;
    }
    if (idx == 0) g_off[NN] = EE;
}

__global__ void k_fill(const int* __restrict__ src, const int* __restrict__ dst) {
    int e = blockIdx.x * blockDim.x + threadIdx.x;
    if (e < EE) {
        int d = dst[e];
        int p = atomicAdd(&g_cursor[d], 1);
        g_srcA[p] = src[e];
    }
}

// ---------------- tf32 tensor-core GEMM (3xTF32 split) ----------------
__device__ __forceinline__ float tf32rn(float x) {
    uint32_t u;
    asm("cvt.rna.tf32.f32 %0, %1;" : "=r"(u) : "f"(x));
    return __uint_as_float(u);
}

__device__ __forceinline__ void mma_tf32(float& c0, float& c1, float& c2, float& c3,
                                         uint32_t a0, uint32_t a1, uint32_t a2, uint32_t a3,
                                         uint32_t b0, uint32_t b1) {
    asm volatile("mma.sync.aligned.m16n8k8.row.col.f32.tf32.tf32.f32 "
                 "{%0,%1,%2,%3},{%4,%5,%6,%7},{%8,%9},{%0,%1,%2,%3};"
                 : "+f"(c0), "+f"(c1), "+f"(c2), "+f"(c3)
                 : "r"(a0), "r"(a1), "r"(a2), "r"(a3), "r"(b0), "r"(b1));
}

#define AST 136  // smem stride: 136 mod 32 = 8 -> conflict-free fragment LDS

// C[N,128] = relu(BN_layer(A))[N,128] @ W[128,128], scaled by dinv[row]
__global__ __launch_bounds__(256) void k_gemm_t(const float* __restrict__ A,
                                                const float* __restrict__ W,
                                                float* __restrict__ C,
                                                int doBN, int statLayer,
                                                const float* __restrict__ gamma,
                                                const float* __restrict__ beta) {
    __shared__ float sAhi[16][AST];
    __shared__ float sAlo[16][AST];
    __shared__ float sBhi[16][AST];
    __shared__ float sBlo[16][AST];
    __shared__ float sScale[HH], sShift[HH];

    int tid = threadIdx.x;
    if (doBN && tid < HH) {
        float is = g_istdL[statLayer * HH + tid] * gamma[tid];
        sScale[tid] = is;
        sShift[tid] = beta[tid] - g_meanL[statLayer * HH + tid] * is;
    }
    __syncthreads();

    int lane = tid & 31, wid = tid >> 5;
    int gid = lane >> 2, tig = lane & 3;
    int warp_m = wid & 3, warp_n = wid >> 2;     // 4 x 2 warp grid
    int mrow = warp_m * 32;
    int ncol0 = warp_n * 64;
    int rowBase = blockIdx.x * 128;

    float acc[2][8][4];
    #pragma unroll
    for (int mt = 0; mt < 2; mt++)
        #pragma unroll
        for (int nt = 0; nt < 8; nt++)
            #pragma unroll
            for (int r = 0; r < 4; r++) acc[mt][nt][r] = 0.f;

    for (int kc = 0; kc < 8; kc++) {
        int gcol = kc * 16;
        float4 av[2]; int arow[2], acol[2];
        #pragma unroll
        for (int i = 0; i < 2; i++) {
            int idx = i * 256 + tid;
            arow[i] = idx & 127;
            acol[i] = (idx >> 7) * 4;
            int gr = rowBase + arow[i];
            float4 v = make_float4(0.f, 0.f, 0.f, 0.f);
            if (gr < NN) v = *(const float4*)(A + (size_t)gr * HH + gcol + acol[i]);
            if (doBN) {
                int cb = gcol + acol[i];
                v.x = fmaxf(0.f, fmaf(v.x, sScale[cb], sShift[cb]));
                v.y = fmaxf(0.f, fmaf(v.y, sScale[cb + 1], sShift[cb + 1]));
                v.z = fmaxf(0.f, fmaf(v.z, sScale[cb + 2], sShift[cb + 2]));
                v.w = fmaxf(0.f, fmaf(v.w, sScale[cb + 3], sShift[cb + 3]));
            }
            av[i] = v;
        }
        float4 wv[2]; int wk[2], wc[2];
        #pragma unroll
        for (int i = 0; i < 2; i++) {
            int idx = i * 256 + tid;
            wk[i] = idx >> 5;
            wc[i] = (idx & 31) * 4;
            wv[i] = *(const float4*)(W + (size_t)(gcol + wk[i]) * HH + wc[i]);
        }
        __syncthreads();
        #pragma unroll
        for (int i = 0; i < 2; i++) {
            float vv[4] = {av[i].x, av[i].y, av[i].z, av[i].w};
            #pragma unroll
            for (int j = 0; j < 4; j++) {
                float hi = tf32rn(vv[j]);
                sAhi[acol[i] + j][arow[i]] = hi;
                sAlo[acol[i] + j][arow[i]] = tf32rn(vv[j] - hi);
            }
            float wvv[4] = {wv[i].x, wv[i].y, wv[i].z, wv[i].w};
            float h0 = tf32rn(wvv[0]), h1 = tf32rn(wvv[1]), h2 = tf32rn(wvv[2]), h3 = tf32rn(wvv[3]);
            *(float4*)&sBhi[wk[i]][wc[i]] = make_float4(h0, h1, h2, h3);
            *(float4*)&sBlo[wk[i]][wc[i]] = make_float4(tf32rn(wvv[0] - h0), tf32rn(wvv[1] - h1),
                                                        tf32rn(wvv[2] - h2), tf32rn(wvv[3] - h3));
        }
        __syncthreads();
        #pragma unroll
        for (int ks = 0; ks < 2; ks++) {
            int kb = ks * 8;
            uint32_t ahi[2][4], alo[2][4];
            #pragma unroll
            for (int mt = 0; mt < 2; mt++) {
                int m0 = mrow + mt * 16 + gid;
                ahi[mt][0] = __float_as_uint(sAhi[kb + tig][m0]);
                ahi[mt][1] = __float_as_uint(sAhi[kb + tig][m0 + 8]);
                ahi[mt][2] = __float_as_uint(sAhi[kb + tig + 4][m0]);
                ahi[mt][3] = __float_as_uint(sAhi[kb + tig + 4][m0 + 8]);
                alo[mt][0] = __float_as_uint(sAlo[kb + tig][m0]);
                alo[mt][1] = __float_as_uint(sAlo[kb + tig][m0 + 8]);
                alo[mt][2] = __float_as_uint(sAlo[kb + tig + 4][m0]);
                alo[mt][3] = __float_as_uint(sAlo[kb + tig + 4][m0 + 8]);
            }
            #pragma unroll
            for (int nt = 0; nt < 8; nt++) {
                int nc = ncol0 + nt * 8 + gid;
                uint32_t bh0 = __float_as_uint(sBhi[kb + tig][nc]);
                uint32_t bh1 = __float_as_uint(sBhi[kb + tig + 4][nc]);
                uint32_t bl0 = __float_as_uint(sBlo[kb + tig][nc]);
                uint32_t bl1 = __float_as_uint(sBlo[kb + tig + 4][nc]);
                #pragma unroll
                for (int mt = 0; mt < 2; mt++) {
                    float* c = acc[mt][nt];
                    mma_tf32(c[0], c[1], c[2], c[3], alo[mt][0], alo[mt][1], alo[mt][2], alo[mt][3], bh0, bh1);
                    mma_tf32(c[0], c[1], c[2], c[3], ahi[mt][0], ahi[mt][1], ahi[mt][2], ahi[mt][3], bl0, bl1);
                    mma_tf32(c[0], c[1], c[2], c[3], ahi[mt][0], ahi[mt][1], ahi[mt][2], ahi[mt][3], bh0, bh1);
                }
            }
        }
        __syncthreads();
    }

    #pragma unroll
    for (int mt = 0; mt < 2; mt++) {
        int r0 = rowBase + mrow + mt * 16 + gid;
        int r1 = r0 + 8;
        float dv0 = (r0 < NN) ? g_dinv[r0] : 0.f;
        float dv1 = (r1 < NN) ? g_dinv[r1] : 0.f;
        #pragma unroll
        for (int nt = 0; nt < 8; nt++) {
            int c = ncol0 + nt * 8 + 2 * tig;
            float* a = acc[mt][nt];
            if (r0 < NN) *(float2*)(C + (size_t)r0 * HH + c) = make_float2(a[0] * dv0, a[1] * dv0);
            if (r1 < NN) *(float2*)(C + (size_t)r1 * HH + c) = make_float2(a[2] * dv1, a[3] * dv1);
        }
    }
}

// ---------------- aggregation (CSR by dst) + fused BN stat accumulation ----------------
// out[d] = dinv[d] * ( sum_{s in N(d)} hs[s] + hs[d] ),  hs = g_hW (already dinv-scaled)
__global__ __launch_bounds__(256) void k_agg(const float* __restrict__ hw,
                                             float* __restrict__ out) {
    __shared__ float s_sum[HH], s_sq[HH];
    int tid = threadIdx.x;
    if (tid < HH) { s_sum[tid] = 0.f; s_sq[tid] = 0.f; }
    __syncthreads();
    int lane = tid & 31;
    int gw = (blockIdx.x * blockDim.x + tid) >> 5;
    int nw = (gridDim.x * blockDim.x) >> 5;
    float lsx = 0.f, lsy = 0.f, lsz = 0.f, lsw = 0.f;
    float lqx = 0.f, lqy = 0.f, lqz = 0.f, lqw = 0.f;
    for (int node = gw; node < NN; node += nw) {
        float4 v = ((const float4*)(hw + (size_t)node * HH))[lane];
        float ax = v.x, ay = v.y, az = v.z, aw = v.w;
        int e0 = __ldg(&g_off[node]), e1 = __ldg(&g_off[node + 1]);
        int e = e0;
        for (; e + 4 <= e1; e += 4) {
            int s0 = __ldg(&g_srcA[e]);
            int s1 = __ldg(&g_srcA[e + 1]);
            int s2 = __ldg(&g_srcA[e + 2]);
            int s3 = __ldg(&g_srcA[e + 3]);
            float4 u0 = ((const float4*)(hw + (size_t)s0 * HH))[lane];
            float4 u1 = ((const float4*)(hw + (size_t)s1 * HH))[lane];
            float4 u2 = ((const float4*)(hw + (size_t)s2 * HH))[lane];
            float4 u3 = ((const float4*)(hw + (size_t)s3 * HH))[lane];
            ax += u0.x + u1.x + u2.x + u3.x;
            ay += u0.y + u1.y + u2.y + u3.y;
            az += u0.z + u1.z + u2.z + u3.z;
            aw += u0.w + u1.w + u2.w + u3.w;
        }
        for (; e < e1; e++) {
            int s0 = __ldg(&g_srcA[e]);
            float4 u0 = ((const float4*)(hw + (size_t)s0 * HH))[lane];
            ax += u0.x; ay += u0.y; az += u0.z; aw += u0.w;
        }
        float dv = g_dinv[node];
        ax *= dv; ay *= dv; az *= dv; aw *= dv;
        ((float4*)(out + (size_t)node * HH))[lane] = make_float4(ax, ay, az, aw);
        lsx += ax; lsy += ay; lsz += az; lsw += aw;
        lqx += ax * ax; lqy += ay * ay; lqz += az * az; lqw += aw * aw;
    }
    int c = lane * 4;
    atomicAdd(&s_sum[c], lsx);     atomicAdd(&s_sum[c + 1], lsy);
    atomicAdd(&s_sum[c + 2], lsz); atomicAdd(&s_sum[c + 3], lsw);
    atomicAdd(&s_sq[c], lqx);      atomicAdd(&s_sq[c + 1], lqy);
    atomicAdd(&s_sq[c + 2], lqz);  atomicAdd(&s_sq[c + 3], lqw);
    __syncthreads();
    if (tid < HH) {
        atomicAdd(&g_stat[tid], s_sum[tid]);
        atomicAdd(&g_stat[HH + tid], s_sq[tid]);
    }
}

__global__ void k_fin(int layer) {  // finalize layer BN stats, re-zero g_stat
    int t = threadIdx.x;
    if (t < HH) {
        float m = g_stat[t] * (1.f / NN);
        float v = g_stat[HH + t] * (1.f / NN) - m * m;
        g_meanL[layer * HH + t] = m;
        g_istdL[layer * HH + t] = rsqrtf(v + EPSV);
        g_stat[t] = 0.f;
        g_stat[HH + t] = 0.f;
    }
}

// per-graph mean pool with fused BN+ReLU
__global__ void k_pool(const float* __restrict__ agg,
                       const float* __restrict__ gamma,
                       const float* __restrict__ beta, int layer) {
    int g = blockIdx.x, c = threadIdx.x;
    int b = g_goff[g], e = g_goff[g + 1];
    float is = g_istdL[layer * HH + c] * gamma[c];
    float sh = beta[c] - g_meanL[layer * HH + c] * is;
    float s = 0.f;
    for (int r = b; r < e; r++) {
        float x = agg[(size_t)r * HH + c];
        s += fmaxf(0.f, fmaf(x, is, sh));
    }
    int n = e - b;
    float cnt = (float)(n > 1 ? n : 1);
    g_pool[g * LH + layer * HH + c] = s / cnt;
}

// ---------------- MLP head ----------------
__global__ void k_lin1(const float* __restrict__ Wl1, const float* __restrict__ bl1) {
    __shared__ float sp[LH];
    int g = blockIdx.x, t = threadIdx.x;
    sp[t]       = g_pool[g * LH + t];
    sp[t + 128] = g_pool[g * LH + t + 128];
    sp[t + 256] = g_pool[g * LH + t + 256];
    __syncthreads();
    float a = bl1[t];
    #pragma unroll 4
    for (int k = 0; k < LH; k++) a = fmaf(sp[k], Wl1[k * HH + t], a);
    g_z[g * HH + t] = a;
}

__global__ void k_bn2() {
    int t = threadIdx.x;
    if (t < HH) {
        float s = 0.f, q = 0.f;
        for (int r = 0; r < GG; r++) {
            float x = g_z[r * HH + t];
            s += x; q += x * x;
        }
        float m = s * (1.f / GG);
        float v = q * (1.f / GG) - m * m;
        g_m2[t] = m;
        g_i2[t] = rsqrtf(v + EPSV);
    }
}

__global__ void k_final(const float* __restrict__ gl, const float* __restrict__ btl,
                        const float* __restrict__ Wl2, const float* __restrict__ bl2,
                        float* __restrict__ out) {
    __shared__ float zr[HH];
    __shared__ float lg[CC];
    __shared__ float s_ls;
    int g = blockIdx.x, t = threadIdx.x;
    float x = g_z[g * HH + t];
    zr[t] = fmaxf(0.f, (x - g_m2[t]) * g_i2[t] * gl[t] + btl[t]);
    __syncthreads();
    if (t < CC) {
        float d = bl2[t];
        #pragma unroll 4
        for (int j = 0; j < HH; j++) d = fmaf(zr[j], Wl2[j * CC + t], d);
        lg[t] = d;
    }
    __syncthreads();
    if (t == 0) {
        float m = lg[0];
        for (int c = 1; c < CC; c++) m = fmaxf(m, lg[c]);
        float se = 0.f;
        for (int c = 0; c < CC; c++) se += expf(lg[c] - m);
        s_ls = m + logf(se);
    }
    __syncthreads();
    if (t < CC) out[g * CC + t] = lg[t] - s_ls;
}

// ---------------- launch (single serial stream) ----------------
extern "C" void kernel_launch(void* const* d_in, const int* in_sizes, int n_in,
                              void* d_out, int out_size) {
    const float* x     = (const float*)d_in[0];
    const int*   ei    = (const int*)d_in[1];     // int32 (JAX x64 disabled)
    const int*   batch = (const int*)d_in[2];
    const float* W1  = (const float*)d_in[3];
    const float* g1  = (const float*)d_in[5];
    const float* bt1 = (const float*)d_in[6];
    const float* Wc  = (const float*)d_in[7];
    const float* gc  = (const float*)d_in[9];
    const float* btc = (const float*)d_in[10];
    const float* Wl1 = (const float*)d_in[11];
    const float* bl1 = (const float*)d_in[12];
    const float* gl  = (const float*)d_in[13];
    const float* btl = (const float*)d_in[14];
    const float* Wl2 = (const float*)d_in[15];
    const float* bl2 = (const float*)d_in[16];
    const int* src = ei;
    const int* dst = ei + EE;

    void *p_hW, *p_aggA, *p_aggB;
    cudaGetSymbolAddress(&p_hW, g_hW);
    cudaGetSymbolAddress(&p_aggA, g_aggA);
    cudaGetSymbolAddress(&p_aggB, g_aggB);
    float* hW   = (float*)p_hW;
    float* aggA = (float*)p_aggA;
    float* aggB = (float*)p_aggB;

    const int GEMM_GRID = (NN + 127) / 128;
    const int AGG_GRID  = 1480;

    // ---- setup: degree count, scan (dinv + goff fused), CSR fill ----
    k_count<<<(EE + 255) / 256, 256>>>(dst);          // launch 1
    s_partial<<<NBLK, 1024>>>();                      // launch 2
    s_add<<<NBLK, 1024>>>(batch);                     // launch 3
    k_fill<<<(EE + 255) / 256, 256>>>(src, dst);      // launch 4

    // ---- layer 0: x -> aggA ----
    k_gemm_t<<<GEMM_GRID, 256>>>(x, W1, hW, 0, 0, (const float*)0, (const float*)0); // launch 5 (profiled)
    k_agg<<<AGG_GRID, 256>>>(hW, aggA);
    k_fin<<<1, 128>>>(0);
    k_pool<<<GG, 128>>>(aggA, g1, bt1, 0);

    // ---- layer 1: BN0(aggA) -> aggB ----
    k_gemm_t<<<GEMM_GRID, 256>>>(aggA, Wc, hW, 1, 0, g1, bt1);
    k_agg<<<AGG_GRID, 256>>>(hW, aggB);
    k_fin<<<1, 128>>>(1);
    k_pool<<<GG, 128>>>(aggB, gc, btc, 1);

    // ---- layer 2: BN1(aggB) -> aggA ----
    k_gemm_t<<<GEMM_GRID, 256>>>(aggB, Wc + HH * HH, hW, 1, 1, gc, btc);
    k_agg<<<AGG_GRID, 256>>>(hW, aggA);
    k_fin<<<1, 128>>>(2);
    k_pool<<<GG, 128>>>(aggA, gc + HH, btc + HH, 2);

    // ---- head ----
    k_lin1<<<GG, 128>>>(Wl1, bl1);
    k_bn2<<<1, 128>>>();
    k_final<<<GG, 128>>>(gl, btl, Wl2, bl2, (float*)d_out);
}

// round 7
// speedup vs baseline: 1.0254x; 1.0254x over previous
#include <cuda_runtime.h>
#include <cuda_fp16.h>
#include <cstdint>

#define NN 100000
#define EE 1600000
#define HH 128
#define GG 512
#define CC 10
#define LH 384   // L*H
#define EPSV 1e-5f
#define NBLK 98  // ceil(NN/1024)

// ---------------- device scratch (no allocations allowed) ----------------
// zero-invariants: g_cnt, g_stat are zero at entry of every call
__device__ __align__(16) __half g_hW16[NN * HH]; // GEMM output, fp16 (dinv-scaled)
__device__ __align__(16) float g_aggA[NN * HH];  // aggregation ping (fp32)
__device__ __align__(16) float g_aggB[NN * HH];  // aggregation pong (fp32)
__device__ float g_dinv[NN];
__device__ int   g_cnt[NN];
__device__ int   g_off[NN + 1];
__device__ int   g_cursor[NN];
__device__ int   g_srcA[EE];
__device__ int   g_bsum[128];
__device__ float g_stat[2 * HH];       // [0:128) sum, [128:256) sumsq
__device__ float g_meanL[3 * HH];      // per-layer BN stats
__device__ float g_istdL[3 * HH];
__device__ int   g_goff[GG + 1];
__device__ float g_pool[GG * LH];
__device__ float g_z[GG * HH];
__device__ float g_m2[HH];
__device__ float g_i2[HH];

// ---------------- setup kernels ----------------
__global__ void k_count(const int* __restrict__ dst) {
    int e = blockIdx.x * blockDim.x + threadIdx.x;
    if (e < EE) atomicAdd(&g_cnt[dst[e]], 1);
}

// block-local exclusive scan + block sums; also writes dinv
__global__ void s_partial() {
    __shared__ int wsum[32];
    int tid = threadIdx.x, lane = tid & 31, wid = tid >> 5;
    int idx = blockIdx.x * 1024 + tid;
    int v = (idx < NN) ? g_cnt[idx] : 0;
    if (idx < NN) g_dinv[idx] = rsqrtf((float)(v + 1));
    int x = v;
    #pragma unroll
    for (int o = 1; o < 32; o <<= 1) {
        int y = __shfl_up_sync(0xffffffffu, x, o);
        if (lane >= o) x += y;
    }
    if (lane == 31) wsum[wid] = x;
    __syncthreads();
    if (wid == 0) {
        int w = wsum[lane];
        int xx = w;
        #pragma unroll
        for (int o = 1; o < 32; o <<= 1) {
            int y = __shfl_up_sync(0xffffffffu, xx, o);
            if (lane >= o) xx += y;
        }
        wsum[lane] = xx - w;
    }
    __syncthreads();
    int incl = x + wsum[wid];
    if (idx < NN) g_off[idx] = incl - v;     // block-local exclusive
    if (tid == 1023) g_bsum[blockIdx.x] = incl;
}

// finalize offsets, init cursor, zero g_cnt, graph offsets via boundary scan
__global__ void s_add(const int* __restrict__ batch) {
    __shared__ int sb[128];
    int tid = threadIdx.x;
    if (tid < 128) sb[tid] = (tid < NBLK) ? g_bsum[tid] : 0;
    __syncthreads();
    #pragma unroll
    for (int o = 1; o < 128; o <<= 1) {
        int v = 0;
        if (tid < 128 && tid >= o) v = sb[tid - o];
        __syncthreads();
        if (tid < 128) sb[tid] += v;
        __syncthreads();
    }
    int bpre = (blockIdx.x > 0) ? sb[blockIdx.x - 1] : 0;
    int idx = blockIdx.x * 1024 + tid;
    if (idx < NN) {
        int off = g_off[idx] + bpre;
        g_off[idx] = off;
        g_cursor[idx] = off;
        g_cnt[idx] = 0;                      // restore zero-invariant
        int b = batch[idx];
        int prev = (idx > 0) ? batch[idx - 1] : -1;
        for (int g = prev + 1; g <= b; g++) g_goff[g] = idx;
        if (idx == NN - 1)
            for (int g = b + 1; g <= GG; g++) g_goff[g] = NN;
    }
    if (idx == 0) g_off[NN] = EE;
}

__global__ void k_fill(const int* __restrict__ src, const int* __restrict__ dst) {
    int e = blockIdx.x * blockDim.x + threadIdx.x;
    if (e < EE) {
        int d = dst[e];
        int p = atomicAdd(&g_cursor[d], 1);
        g_srcA[p] = src[e];
    }
}

// ---------------- tf32 tensor-core GEMM (3xTF32 split) ----------------
__device__ __forceinline__ float tf32rn(float x) {
    uint32_t u;
    asm("cvt.rna.tf32.f32 %0, %1;" : "=r"(u) : "f"(x));
    return __uint_as_float(u);
}

__device__ __forceinline__ void mma_tf32(float& c0, float& c1, float& c2, float& c3,
                                         uint32_t a0, uint32_t a1, uint32_t a2, uint32_t a3,
                                         uint32_t b0, uint32_t b1) {
    asm volatile("mma.sync.aligned.m16n8k8.row.col.f32.tf32.tf32.f32 "
                 "{%0,%1,%2,%3},{%4,%5,%6,%7},{%8,%9},{%0,%1,%2,%3};"
                 : "+f"(c0), "+f"(c1), "+f"(c2), "+f"(c3)
                 : "r"(a0), "r"(a1), "r"(a2), "r"(a3), "r"(b0), "r"(b1));
}

#define AST 136  // smem stride: 136 mod 32 = 8 -> conflict-free fragment LDS

// C16[N,128] = fp16( dinv[row] * (relu(BN_layer(A))[N,128] @ W[128,128]) )
__global__ __launch_bounds__(256) void k_gemm_t(const float* __restrict__ A,
                                                const float* __restrict__ W,
                                                __half* __restrict__ C16,
                                                int doBN, int statLayer,
                                                const float* __restrict__ gamma,
                                                const float* __restrict__ beta) {
    __shared__ float sAhi[16][AST];
    __shared__ float sAlo[16][AST];
    __shared__ float sBhi[16][AST];
    __shared__ float sBlo[16][AST];
    __shared__ float sScale[HH], sShift[HH];

    int tid = threadIdx.x;
    if (doBN && tid < HH) {
        float is = g_istdL[statLayer * HH + tid] * gamma[tid];
        sScale[tid] = is;
        sShift[tid] = beta[tid] - g_meanL[statLayer * HH + tid] * is;
    }
    __syncthreads();

    int lane = tid & 31, wid = tid >> 5;
    int gid = lane >> 2, tig = lane & 3;
    int warp_m = wid & 3, warp_n = wid >> 2;     // 4 x 2 warp grid
    int mrow = warp_m * 32;
    int ncol0 = warp_n * 64;
    int rowBase = blockIdx.x * 128;

    float acc[2][8][4];
    #pragma unroll
    for (int mt = 0; mt < 2; mt++)
        #pragma unroll
        for (int nt = 0; nt < 8; nt++)
            #pragma unroll
            for (int r = 0; r < 4; r++) acc[mt][nt][r] = 0.f;

    for (int kc = 0; kc < 8; kc++) {
        int gcol = kc * 16;
        float4 av[2]; int arow[2], acol[2];
        #pragma unroll
        for (int i = 0; i < 2; i++) {
            int idx = i * 256 + tid;
            arow[i] = idx & 127;
            acol[i] = (idx >> 7) * 4;
            int gr = rowBase + arow[i];
            float4 v = make_float4(0.f, 0.f, 0.f, 0.f);
            if (gr < NN) v = *(const float4*)(A + (size_t)gr * HH + gcol + acol[i]);
            if (doBN) {
                int cb = gcol + acol[i];
                v.x = fmaxf(0.f, fmaf(v.x, sScale[cb], sShift[cb]));
                v.y = fmaxf(0.f, fmaf(v.y, sScale[cb + 1], sShift[cb + 1]));
                v.z = fmaxf(0.f, fmaf(v.z, sScale[cb + 2], sShift[cb + 2]));
                v.w = fmaxf(0.f, fmaf(v.w, sScale[cb + 3], sShift[cb + 3]));
            }
            av[i] = v;
        }
        float4 wv[2]; int wk[2], wc[2];
        #pragma unroll
        for (int i = 0; i < 2; i++) {
            int idx = i * 256 + tid;
            wk[i] = idx >> 5;
            wc[i] = (idx & 31) * 4;
            wv[i] = *(const float4*)(W + (size_t)(gcol + wk[i]) * HH + wc[i]);
        }
        __syncthreads();
        #pragma unroll
        for (int i = 0; i < 2; i++) {
            float vv[4] = {av[i].x, av[i].y, av[i].z, av[i].w};
            #pragma unroll
            for (int j = 0; j < 4; j++) {
                float hi = tf32rn(vv[j]);
                sAhi[acol[i] + j][arow[i]] = hi;
                sAlo[acol[i] + j][arow[i]] = tf32rn(vv[j] - hi);
            }
            float wvv[4] = {wv[i].x, wv[i].y, wv[i].z, wv[i].w};
            float h0 = tf32rn(wvv[0]), h1 = tf32rn(wvv[1]), h2 = tf32rn(wvv[2]), h3 = tf32rn(wvv[3]);
            *(float4*)&sBhi[wk[i]][wc[i]] = make_float4(h0, h1, h2, h3);
            *(float4*)&sBlo[wk[i]][wc[i]] = make_float4(tf32rn(wvv[0] - h0), tf32rn(wvv[1] - h1),
                                                        tf32rn(wvv[2] - h2), tf32rn(wvv[3] - h3));
        }
        __syncthreads();
        #pragma unroll
        for (int ks = 0; ks < 2; ks++) {
            int kb = ks * 8;
            uint32_t ahi[2][4], alo[2][4];
            #pragma unroll
            for (int mt = 0; mt < 2; mt++) {
                int m0 = mrow + mt * 16 + gid;
                ahi[mt][0] = __float_as_uint(sAhi[kb + tig][m0]);
                ahi[mt][1] = __float_as_uint(sAhi[kb + tig][m0 + 8]);
                ahi[mt][2] = __float_as_uint(sAhi[kb + tig + 4][m0]);
                ahi[mt][3] = __float_as_uint(sAhi[kb + tig + 4][m0 + 8]);
                alo[mt][0] = __float_as_uint(sAlo[kb + tig][m0]);
                alo[mt][1] = __float_as_uint(sAlo[kb + tig][m0 + 8]);
                alo[mt][2] = __float_as_uint(sAlo[kb + tig + 4][m0]);
                alo[mt][3] = __float_as_uint(sAlo[kb + tig + 4][m0 + 8]);
            }
            #pragma unroll
            for (int nt = 0; nt < 8; nt++) {
                int nc = ncol0 + nt * 8 + gid;
                uint32_t bh0 = __float_as_uint(sBhi[kb + tig][nc]);
                uint32_t bh1 = __float_as_uint(sBhi[kb + tig + 4][nc]);
                uint32_t bl0 = __float_as_uint(sBlo[kb + tig][nc]);
                uint32_t bl1 = __float_as_uint(sBlo[kb + tig + 4][nc]);
                #pragma unroll
                for (int mt = 0; mt < 2; mt++) {
                    float* c = acc[mt][nt];
                    mma_tf32(c[0], c[1], c[2], c[3], alo[mt][0], alo[mt][1], alo[mt][2], alo[mt][3], bh0, bh1);
                    mma_tf32(c[0], c[1], c[2], c[3], ahi[mt][0], ahi[mt][1], ahi[mt][2], ahi[mt][3], bl0, bl1);
                    mma_tf32(c[0], c[1], c[2], c[3], ahi[mt][0], ahi[mt][1], ahi[mt][2], ahi[mt][3], bh0, bh1);
                }
            }
        }
        __syncthreads();
    }

    // epilogue: scale by dinv[row], convert fp16, write
    #pragma unroll
    for (int mt = 0; mt < 2; mt++) {
        int r0 = rowBase + mrow + mt * 16 + gid;
        int r1 = r0 + 8;
        float dv0 = (r0 < NN) ? g_dinv[r0] : 0.f;
        float dv1 = (r1 < NN) ? g_dinv[r1] : 0.f;
        #pragma unroll
        for (int nt = 0; nt < 8; nt++) {
            int c = ncol0 + nt * 8 + 2 * tig;
            float* a = acc[mt][nt];
            if (r0 < NN) *(__half2*)(C16 + (size_t)r0 * HH + c) = __floats2half2_rn(a[0] * dv0, a[1] * dv0);
            if (r1 < NN) *(__half2*)(C16 + (size_t)r1 * HH + c) = __floats2half2_rn(a[2] * dv1, a[3] * dv1);
        }
    }
}

// ---------------- aggregation (CSR by dst, fp16 source) + BN stats ----------------
// out[d] = dinv[d] * ( sum_{s in N(d)} hs[s] + hs[d] ),  hs = g_hW16 (dinv-scaled fp16)
__global__ __launch_bounds__(256) void k_agg(const __half* __restrict__ hw,
                                             float* __restrict__ out) {
    __shared__ float s_sum[HH], s_sq[HH];
    int tid = threadIdx.x;
    if (tid < HH) { s_sum[tid] = 0.f; s_sq[tid] = 0.f; }
    __syncthreads();
    int lane = tid & 31;
    int col = lane * 4;   // 4 halves (= 1 uint2) per lane, 32 lanes = 128 cols
    int gw = (blockIdx.x * blockDim.x + tid) >> 5;
    int nw = (gridDim.x * blockDim.x) >> 5;
    float lsx = 0.f, lsy = 0.f, lsz = 0.f, lsw = 0.f;
    float lqx = 0.f, lqy = 0.f, lqz = 0.f, lqw = 0.f;
    for (int node = gw; node < NN; node += nw) {
        uint2 rv = *(const uint2*)(hw + (size_t)node * HH + col);
        float2 f0 = __half22float2(*(__half2*)&rv.x);
        float2 f1 = __half22float2(*(__half2*)&rv.y);
        float ax = f0.x, ay = f0.y, az = f1.x, aw = f1.y;
        int e0 = __ldg(&g_off[node]), e1 = __ldg(&g_off[node + 1]);
        int e = e0;
        for (; e + 4 <= e1; e += 4) {
            int s0 = __ldg(&g_srcA[e]);
            int s1 = __ldg(&g_srcA[e + 1]);
            int s2 = __ldg(&g_srcA[e + 2]);
            int s3 = __ldg(&g_srcA[e + 3]);
            uint2 r0 = *(const uint2*)(hw + (size_t)s0 * HH + col);
            uint2 r1 = *(const uint2*)(hw + (size_t)s1 * HH + col);
            uint2 r2 = *(const uint2*)(hw + (size_t)s2 * HH + col);
            uint2 r3 = *(const uint2*)(hw + (size_t)s3 * HH + col);
            float2 a0 = __half22float2(*(__half2*)&r0.x), b0 = __half22float2(*(__half2*)&r0.y);
            float2 a1 = __half22float2(*(__half2*)&r1.x), b1 = __half22float2(*(__half2*)&r1.y);
            float2 a2 = __half22float2(*(__half2*)&r2.x), b2 = __half22float2(*(__half2*)&r2.y);
            float2 a3 = __half22float2(*(__half2*)&r3.x), b3 = __half22float2(*(__half2*)&r3.y);
            ax += a0.x + a1.x + a2.x + a3.x;
            ay += a0.y + a1.y + a2.y + a3.y;
            az += b0.x + b1.x + b2.x + b3.x;
            aw += b0.y + b1.y + b2.y + b3.y;
        }
        for (; e < e1; e++) {
            int s0 = __ldg(&g_srcA[e]);
            uint2 r0 = *(const uint2*)(hw + (size_t)s0 * HH + col);
            float2 a0 = __half22float2(*(__half2*)&r0.x), b0 = __half22float2(*(__half2*)&r0.y);
            ax += a0.x; ay += a0.y; az += b0.x; aw += b0.y;
        }
        float dv = g_dinv[node];
        ax *= dv; ay *= dv; az *= dv; aw *= dv;
        ((float4*)(out + (size_t)node * HH))[lane] = make_float4(ax, ay, az, aw);
        lsx += ax; lsy += ay; lsz += az; lsw += aw;
        lqx += ax * ax; lqy += ay * ay; lqz += az * az; lqw += aw * aw;
    }
    atomicAdd(&s_sum[col], lsx);     atomicAdd(&s_sum[col + 1], lsy);
    atomicAdd(&s_sum[col + 2], lsz); atomicAdd(&s_sum[col + 3], lsw);
    atomicAdd(&s_sq[col], lqx);      atomicAdd(&s_sq[col + 1], lqy);
    atomicAdd(&s_sq[col + 2], lqz);  atomicAdd(&s_sq[col + 3], lqw);
    __syncthreads();
    if (tid < HH) {
        atomicAdd(&g_stat[tid], s_sum[tid]);
        atomicAdd(&g_stat[HH + tid], s_sq[tid]);
    }
}

__global__ void k_fin(int layer) {  // finalize layer BN stats, re-zero g_stat
    int t = threadIdx.x;
    if (t < HH) {
        float m = g_stat[t] * (1.f / NN);
        float v = g_stat[HH + t] * (1.f / NN) - m * m;
        g_meanL[layer * HH + t] = m;
        g_istdL[layer * HH + t] = rsqrtf(v + EPSV);
        g_stat[t] = 0.f;
        g_stat[HH + t] = 0.f;
    }
}

// per-graph mean pool with fused BN+ReLU
__global__ void k_pool(const float* __restrict__ agg,
                       const float* __restrict__ gamma,
                       const float* __restrict__ beta, int layer) {
    int g = blockIdx.x, c = threadIdx.x;
    int b = g_goff[g], e = g_goff[g + 1];
    float is = g_istdL[layer * HH + c] * gamma[c];
    float sh = beta[c] - g_meanL[layer * HH + c] * is;
    float s = 0.f;
    for (int r = b; r < e; r++) {
        float x = agg[(size_t)r * HH + c];
        s += fmaxf(0.f, fmaf(x, is, sh));
    }
    int n = e - b;
    float cnt = (float)(n > 1 ? n : 1);
    g_pool[g * LH + layer * HH + c] = s / cnt;
}

// ---------------- MLP head ----------------
__global__ void k_lin1(const float* __restrict__ Wl1, const float* __restrict__ bl1) {
    __shared__ float sp[LH];
    int g = blockIdx.x, t = threadIdx.x;
    sp[t]       = g_pool[g * LH + t];
    sp[t + 128] = g_pool[g * LH + t + 128];
    sp[t + 256] = g_pool[g * LH + t + 256];
    __syncthreads();
    float a = bl1[t];
    #pragma unroll 4
    for (int k = 0; k < LH; k++) a = fmaf(sp[k], Wl1[k * HH + t], a);
    g_z[g * HH + t] = a;
}

__global__ void k_bn2() {
    int t = threadIdx.x;
    if (t < HH) {
        float s = 0.f, q = 0.f;
        for (int r = 0; r < GG; r++) {
            float x = g_z[r * HH + t];
            s += x; q += x * x;
        }
        float m = s * (1.f / GG);
        float v = q * (1.f / GG) - m * m;
        g_m2[t] = m;
        g_i2[t] = rsqrtf(v + EPSV);
    }
}

__global__ void k_final(const float* __restrict__ gl, const float* __restrict__ btl,
                        const float* __restrict__ Wl2, const float* __restrict__ bl2,
                        float* __restrict__ out) {
    __shared__ float zr[HH];
    __shared__ float lg[CC];
    __shared__ float s_ls;
    int g = blockIdx.x, t = threadIdx.x;
    float x = g_z[g * HH + t];
    zr[t] = fmaxf(0.f, (x - g_m2[t]) * g_i2[t] * gl[t] + btl[t]);
    __syncthreads();
    if (t < CC) {
        float d = bl2[t];
        #pragma unroll 4
        for (int j = 0; j < HH; j++) d = fmaf(zr[j], Wl2[j * CC + t], d);
        lg[t] = d;
    }
    __syncthreads();
    if (t == 0) {
        float m = lg[0];
        for (int c = 1; c < CC; c++) m = fmaxf(m, lg[c]);
        float se = 0.f;
        for (int c = 0; c < CC; c++) se += expf(lg[c] - m);
        s_ls = m + logf(se);
    }
    __syncthreads();
    if (t < CC) out[g * CC + t] = lg[t] - s_ls;
}

// ---------------- launch (single serial stream) ----------------
extern "C" void kernel_launch(void* const* d_in, const int* in_sizes, int n_in,
                              void* d_out, int out_size) {
    const float* x     = (const float*)d_in[0];
    const int*   ei    = (const int*)d_in[1];     // int32 (JAX x64 disabled)
    const int*   batch = (const int*)d_in[2];
    const float* W1  = (const float*)d_in[3];
    const float* g1  = (const float*)d_in[5];
    const float* bt1 = (const float*)d_in[6];
    const float* Wc  = (const float*)d_in[7];
    const float* gc  = (const float*)d_in[9];
    const float* btc = (const float*)d_in[10];
    const float* Wl1 = (const float*)d_in[11];
    const float* bl1 = (const float*)d_in[12];
    const float* gl  = (const float*)d_in[13];
    const float* btl = (const float*)d_in[14];
    const float* Wl2 = (const float*)d_in[15];
    const float* bl2 = (const float*)d_in[16];
    const int* src = ei;
    const int* dst = ei + EE;

    void *p_hW, *p_aggA, *p_aggB;
    cudaGetSymbolAddress(&p_hW, g_hW16);
    cudaGetSymbolAddress(&p_aggA, g_aggA);
    cudaGetSymbolAddress(&p_aggB, g_aggB);
    __half* hW  = (__half*)p_hW;
    float* aggA = (float*)p_aggA;
    float* aggB = (float*)p_aggB;

    const int GEMM_GRID = (NN + 127) / 128;
    const int AGG_GRID  = 1480;

    // ---- setup: degree count, scan (dinv + goff fused), CSR fill ----
    k_count<<<(EE + 255) / 256, 256>>>(dst);          // launch 1
    s_partial<<<NBLK, 1024>>>();                      // launch 2
    s_add<<<NBLK, 1024>>>(batch);                     // launch 3
    k_fill<<<(EE + 255) / 256, 256>>>(src, dst);      // launch 4

    // ---- layer 0: x -> aggA ----
    k_gemm_t<<<GEMM_GRID, 256>>>(x, W1, hW, 0, 0, (const float*)0, (const float*)0); // launch 5 (profiled)
    k_agg<<<AGG_GRID, 256>>>(hW, aggA);
    k_fin<<<1, 128>>>(0);
    k_pool<<<GG, 128>>>(aggA, g1, bt1, 0);

    // ---- layer 1: BN0(aggA) -> aggB ----
    k_gemm_t<<<GEMM_GRID, 256>>>(aggA, Wc, hW, 1, 0, g1, bt1);
    k_agg<<<AGG_GRID, 256>>>(hW, aggB);
    k_fin<<<1, 128>>>(1);
    k_pool<<<GG, 128>>>(aggB, gc, btc, 1);

    // ---- layer 2: BN1(aggB) -> aggA ----
    k_gemm_t<<<GEMM_GRID, 256>>>(aggB, Wc + HH * HH, hW, 1, 1, gc, btc);
    k_agg<<<AGG_GRID, 256>>>(hW, aggA);
    k_fin<<<1, 128>>>(2);
    k_pool<<<GG, 128>>>(aggA, gc + HH, btc + HH, 2);

    // ---- head ----
    k_lin1<<<GG, 128>>>(Wl1, bl1);
    k_bn2<<<1, 128>>>();
    k_final<<<GG, 128>>>(gl, btl, Wl2, bl2, (float*)d_out);
}

// round 8
// speedup vs baseline: 1.0845x; 1.0577x over previous
#include <cuda_runtime.h>
#include <cuda_fp16.h>
#include <cstdint>

#define NN 100000
#define EE 1600000
#define HH 128
#define GG 512
#define CC 10
#define LH 384   // L*H
#define EPSV 1e-5f
#define NBLK 98  // ceil(NN/1024)

// ---------------- device scratch (no allocations allowed) ----------------
// zero-invariants: g_cnt, g_stat are zero at entry of every call
__device__ __align__(16) __half g_hW16[NN * HH]; // GEMM output, fp16 (dinv-scaled)
__device__ __align__(16) float g_aggA[NN * HH];  // aggregation ping (fp32)
__device__ __align__(16) float g_aggB[NN * HH];  // aggregation pong (fp32)
__device__ float g_dinv[NN];
__device__ int   g_cnt[NN];
__device__ int   g_off[NN + 1];
__device__ int   g_cursor[NN];
__device__ int   g_srcA[EE];
__device__ int   g_bsum[128];
__device__ float g_stat[2 * HH];       // [0:128) sum, [128:256) sumsq
__device__ float g_meanL[3 * HH];      // per-layer BN stats
__device__ float g_istdL[3 * HH];
__device__ int   g_goff[GG + 1];
__device__ float g_pool[GG * LH];
__device__ float g_z[GG * HH];
__device__ float g_m2[HH];
__device__ float g_i2[HH];

// ---------------- setup kernels ----------------
__global__ void k_count(const int* __restrict__ dst) {
    int e = blockIdx.x * blockDim.x + threadIdx.x;
    if (e < EE) atomicAdd(&g_cnt[dst[e]], 1);
}

// block-local exclusive scan + block sums; also writes dinv
__global__ void s_partial() {
    __shared__ int wsum[32];
    int tid = threadIdx.x, lane = tid & 31, wid = tid >> 5;
    int idx = blockIdx.x * 1024 + tid;
    int v = (idx < NN) ? g_cnt[idx] : 0;
    if (idx < NN) g_dinv[idx] = rsqrtf((float)(v + 1));
    int x = v;
    #pragma unroll
    for (int o = 1; o < 32; o <<= 1) {
        int y = __shfl_up_sync(0xffffffffu, x, o);
        if (lane >= o) x += y;
    }
    if (lane == 31) wsum[wid] = x;
    __syncthreads();
    if (wid == 0) {
        int w = wsum[lane];
        int xx = w;
        #pragma unroll
        for (int o = 1; o < 32; o <<= 1) {
            int y = __shfl_up_sync(0xffffffffu, xx, o);
            if (lane >= o) xx += y;
        }
        wsum[lane] = xx - w;
    }
    __syncthreads();
    int incl = x + wsum[wid];
    if (idx < NN) g_off[idx] = incl - v;     // block-local exclusive
    if (tid == 1023) g_bsum[blockIdx.x] = incl;
}

// finalize offsets, init cursor, zero g_cnt, graph offsets via boundary scan
__global__ void s_add(const int* __restrict__ batch) {
    __shared__ int sb[128];
    int tid = threadIdx.x;
    if (tid < 128) sb[tid] = (tid < NBLK) ? g_bsum[tid] : 0;
    __syncthreads();
    #pragma unroll
    for (int o = 1; o < 128; o <<= 1) {
        int v = 0;
        if (tid < 128 && tid >= o) v = sb[tid - o];
        __syncthreads();
        if (tid < 128) sb[tid] += v;
        __syncthreads();
    }
    int bpre = (blockIdx.x > 0) ? sb[blockIdx.x - 1] : 0;
    int idx = blockIdx.x * 1024 + tid;
    if (idx < NN) {
        int off = g_off[idx] + bpre;
        g_off[idx] = off;
        g_cursor[idx] = off;
        g_cnt[idx] = 0;                      // restore zero-invariant
        int b = batch[idx];
        int prev = (idx > 0) ? batch[idx - 1] : -1;
        for (int g = prev + 1; g <= b; g++) g_goff[g] = idx;
        if (idx == NN - 1)
            for (int g = b + 1; g <= GG; g++) g_goff[g] = NN;
    }
    if (idx == 0) g_off[NN] = EE;
}

__global__ void k_fill(const int* __restrict__ src, const int* __restrict__ dst) {
    int e = blockIdx.x * blockDim.x + threadIdx.x;
    if (e < EE) {
        int d = dst[e];
        int p = atomicAdd(&g_cursor[d], 1);
        g_srcA[p] = src[e];
    }
}

// ---------------- tf32 tensor-core GEMM (3xTF32 split) ----------------
__device__ __forceinline__ float tf32rn(float x) {
    uint32_t u;
    asm("cvt.rna.tf32.f32 %0, %1;" : "=r"(u) : "f"(x));
    return __uint_as_float(u);
}

__device__ __forceinline__ void mma_tf32(float& c0, float& c1, float& c2, float& c3,
                                         uint32_t a0, uint32_t a1, uint32_t a2, uint32_t a3,
                                         uint32_t b0, uint32_t b1) {
    asm volatile("mma.sync.aligned.m16n8k8.row.col.f32.tf32.tf32.f32 "
                 "{%0,%1,%2,%3},{%4,%5,%6,%7},{%8,%9},{%0,%1,%2,%3};"
                 : "+f"(c0), "+f"(c1), "+f"(c2), "+f"(c3)
                 : "r"(a0), "r"(a1), "r"(a2), "r"(a3), "r"(b0), "r"(b1));
}

#define AST 136  // smem stride: 136 mod 32 = 8 -> conflict-free fragment LDS

// C16[N,128] = fp16( dinv[row] * (relu(BN_layer(A))[N,128] @ W[128,128]) )
__global__ __launch_bounds__(256) void k_gemm_t(const float* __restrict__ A,
                                                const float* __restrict__ W,
                                                __half* __restrict__ C16,
                                                int doBN, int statLayer,
                                                const float* __restrict__ gamma,
                                                const float* __restrict__ beta) {
    __shared__ float sAhi[16][AST];
    __shared__ float sAlo[16][AST];
    __shared__ float sBhi[16][AST];
    __shared__ float sBlo[16][AST];
    __shared__ float sScale[HH], sShift[HH];

    int tid = threadIdx.x;
    if (doBN && tid < HH) {
        float is = g_istdL[statLayer * HH + tid] * gamma[tid];
        sScale[tid] = is;
        sShift[tid] = beta[tid] - g_meanL[statLayer * HH + tid] * is;
    }
    __syncthreads();

    int lane = tid & 31, wid = tid >> 5;
    int gid = lane >> 2, tig = lane & 3;
    int warp_m = wid & 3, warp_n = wid >> 2;     // 4 x 2 warp grid
    int mrow = warp_m * 32;
    int ncol0 = warp_n * 64;
    int rowBase = blockIdx.x * 128;

    float acc[2][8][4];
    #pragma unroll
    for (int mt = 0; mt < 2; mt++)
        #pragma unroll
        for (int nt = 0; nt < 8; nt++)
            #pragma unroll
            for (int r = 0; r < 4; r++) acc[mt][nt][r] = 0.f;

    for (int kc = 0; kc < 8; kc++) {
        int gcol = kc * 16;
        float4 av[2]; int arow[2], acol[2];
        #pragma unroll
        for (int i = 0; i < 2; i++) {
            int idx = i * 256 + tid;
            arow[i] = idx & 127;
            acol[i] = (idx >> 7) * 4;
            int gr = rowBase + arow[i];
            float4 v = make_float4(0.f, 0.f, 0.f, 0.f);
            if (gr < NN) v = *(const float4*)(A + (size_t)gr * HH + gcol + acol[i]);
            if (doBN) {
                int cb = gcol + acol[i];
                v.x = fmaxf(0.f, fmaf(v.x, sScale[cb], sShift[cb]));
                v.y = fmaxf(0.f, fmaf(v.y, sScale[cb + 1], sShift[cb + 1]));
                v.z = fmaxf(0.f, fmaf(v.z, sScale[cb + 2], sShift[cb + 2]));
                v.w = fmaxf(0.f, fmaf(v.w, sScale[cb + 3], sShift[cb + 3]));
            }
            av[i] = v;
        }
        float4 wv[2]; int wk[2], wc[2];
        #pragma unroll
        for (int i = 0; i < 2; i++) {
            int idx = i * 256 + tid;
            wk[i] = idx >> 5;
            wc[i] = (idx & 31) * 4;
            wv[i] = *(const float4*)(W + (size_t)(gcol + wk[i]) * HH + wc[i]);
        }
        __syncthreads();
        #pragma unroll
        for (int i = 0; i < 2; i++) {
            float vv[4] = {av[i].x, av[i].y, av[i].z, av[i].w};
            #pragma unroll
            for (int j = 0; j < 4; j++) {
                float hi = tf32rn(vv[j]);
                sAhi[acol[i] + j][arow[i]] = hi;
                sAlo[acol[i] + j][arow[i]] = tf32rn(vv[j] - hi);
            }
            float wvv[4] = {wv[i].x, wv[i].y, wv[i].z, wv[i].w};
            float h0 = tf32rn(wvv[0]), h1 = tf32rn(wvv[1]), h2 = tf32rn(wvv[2]), h3 = tf32rn(wvv[3]);
            *(float4*)&sBhi[wk[i]][wc[i]] = make_float4(h0, h1, h2, h3);
            *(float4*)&sBlo[wk[i]][wc[i]] = make_float4(tf32rn(wvv[0] - h0), tf32rn(wvv[1] - h1),
                                                        tf32rn(wvv[2] - h2), tf32rn(wvv[3] - h3));
        }
        __syncthreads();
        #pragma unroll
        for (int ks = 0; ks < 2; ks++) {
            int kb = ks * 8;
            uint32_t ahi[2][4], alo[2][4];
            #pragma unroll
            for (int mt = 0; mt < 2; mt++) {
                int m0 = mrow + mt * 16 + gid;
                ahi[mt][0] = __float_as_uint(sAhi[kb + tig][m0]);
                ahi[mt][1] = __float_as_uint(sAhi[kb + tig][m0 + 8]);
                ahi[mt][2] = __float_as_uint(sAhi[kb + tig + 4][m0]);
                ahi[mt][3] = __float_as_uint(sAhi[kb + tig + 4][m0 + 8]);
                alo[mt][0] = __float_as_uint(sAlo[kb + tig][m0]);
                alo[mt][1] = __float_as_uint(sAlo[kb + tig][m0 + 8]);
                alo[mt][2] = __float_as_uint(sAlo[kb + tig + 4][m0]);
                alo[mt][3] = __float_as_uint(sAlo[kb + tig + 4][m0 + 8]);
            }
            #pragma unroll
            for (int nt = 0; nt < 8; nt++) {
                int nc = ncol0 + nt * 8 + gid;
                uint32_t bh0 = __float_as_uint(sBhi[kb + tig][nc]);
                uint32_t bh1 = __float_as_uint(sBhi[kb + tig + 4][nc]);
                uint32_t bl0 = __float_as_uint(sBlo[kb + tig][nc]);
                uint32_t bl1 = __float_as_uint(sBlo[kb + tig + 4][nc]);
                #pragma unroll
                for (int mt = 0; mt < 2; mt++) {
                    float* c = acc[mt][nt];
                    mma_tf32(c[0], c[1], c[2], c[3], alo[mt][0], alo[mt][1], alo[mt][2], alo[mt][3], bh0, bh1);
                    mma_tf32(c[0], c[1], c[2], c[3], ahi[mt][0], ahi[mt][1], ahi[mt][2], ahi[mt][3], bl0, bl1);
                    mma_tf32(c[0], c[1], c[2], c[3], ahi[mt][0], ahi[mt][1], ahi[mt][2], ahi[mt][3], bh0, bh1);
                }
            }
        }
        __syncthreads();
    }

    // epilogue: scale by dinv[row], convert fp16, write
    #pragma unroll
    for (int mt = 0; mt < 2; mt++) {
        int r0 = rowBase + mrow + mt * 16 + gid;
        int r1 = r0 + 8;
        float dv0 = (r0 < NN) ? g_dinv[r0] : 0.f;
        float dv1 = (r1 < NN) ? g_dinv[r1] : 0.f;
        #pragma unroll
        for (int nt = 0; nt < 8; nt++) {
            int c = ncol0 + nt * 8 + 2 * tig;
            float* a = acc[mt][nt];
            if (r0 < NN) *(__half2*)(C16 + (size_t)r0 * HH + c) = __floats2half2_rn(a[0] * dv0, a[1] * dv0);
            if (r1 < NN) *(__half2*)(C16 + (size_t)r1 * HH + c) = __floats2half2_rn(a[2] * dv1, a[3] * dv1);
        }
    }
}

// ---------------- aggregation: software-pipelined CSR gather + BN stats ----------------
// out[d] = dinv[d] * ( sum_{s in N(d)} hs[s] + hs[d] ),  hs = g_hW16 (dinv-scaled fp16)
#define AGG_GATHER(dst4, sidx) \
    { uint2 _r = *(const uint2*)(hw + (size_t)(sidx) * HH + col); dst4 = _r; }
#define AGG_ACC(r) \
    { float2 _a = __half22float2(*(__half2*)&(r).x); \
      float2 _b = __half22float2(*(__half2*)&(r).y); \
      ax += _a.x; ay += _a.y; az += _b.x; aw += _b.y; }

__global__ __launch_bounds__(256) void k_agg(const __half* __restrict__ hw,
                                             float* __restrict__ out) {
    __shared__ float s_sum[HH], s_sq[HH];
    int tid = threadIdx.x;
    if (tid < HH) { s_sum[tid] = 0.f; s_sq[tid] = 0.f; }
    __syncthreads();
    int lane = tid & 31;
    int col = lane * 4;   // 4 halves (= 1 uint2) per lane, 32 lanes = 128 cols
    int gw = (blockIdx.x * blockDim.x + tid) >> 5;
    int nw = (gridDim.x * blockDim.x) >> 5;
    float lsx = 0.f, lsy = 0.f, lsz = 0.f, lsw = 0.f;
    float lqx = 0.f, lqy = 0.f, lqz = 0.f, lqw = 0.f;
    for (int node = gw; node < NN; node += nw) {
        uint2 rv;
        AGG_GATHER(rv, node);
        float2 f0 = __half22float2(*(__half2*)&rv.x);
        float2 f1 = __half22float2(*(__half2*)&rv.y);
        float ax = f0.x, ay = f0.y, az = f1.x, aw = f1.y;
        int e0 = __ldg(&g_off[node]), e1 = __ldg(&g_off[node + 1]);
        int deg = e1 - e0;
        int nf = deg >> 2;             // number of full 4-edge groups
        if (nf >= 2) {
            // 2-deep pipeline: idx one group ahead, gathers one group in flight
            int s0 = __ldg(&g_srcA[e0]),     s1 = __ldg(&g_srcA[e0 + 1]);
            int s2 = __ldg(&g_srcA[e0 + 2]), s3 = __ldg(&g_srcA[e0 + 3]);
            uint2 p0, p1, p2, p3;
            AGG_GATHER(p0, s0); AGG_GATHER(p1, s1); AGG_GATHER(p2, s2); AGG_GATHER(p3, s3);
            int t0 = __ldg(&g_srcA[e0 + 4]), t1 = __ldg(&g_srcA[e0 + 5]);
            int t2 = __ldg(&g_srcA[e0 + 6]), t3 = __ldg(&g_srcA[e0 + 7]);
            int e = e0 + 8;
            int iters = nf - 2;
            while (iters > 0) {
                uint2 q0, q1, q2, q3;
                AGG_GATHER(q0, t0); AGG_GATHER(q1, t1); AGG_GATHER(q2, t2); AGG_GATHER(q3, t3);
                t0 = __ldg(&g_srcA[e]);     t1 = __ldg(&g_srcA[e + 1]);
                t2 = __ldg(&g_srcA[e + 2]); t3 = __ldg(&g_srcA[e + 3]);
                AGG_ACC(p0); AGG_ACC(p1); AGG_ACC(p2); AGG_ACC(p3);
                p0 = q0; p1 = q1; p2 = q2; p3 = q3;
                e += 4; iters--;
            }
            // drain: last group's gathers (t), then accumulate both pending groups
            uint2 q0, q1, q2, q3;
            AGG_GATHER(q0, t0); AGG_GATHER(q1, t1); AGG_GATHER(q2, t2); AGG_GATHER(q3, t3);
            AGG_ACC(p0); AGG_ACC(p1); AGG_ACC(p2); AGG_ACC(p3);
            AGG_ACC(q0); AGG_ACC(q1); AGG_ACC(q2); AGG_ACC(q3);
        } else if (nf == 1) {
            int s0 = __ldg(&g_srcA[e0]),     s1 = __ldg(&g_srcA[e0 + 1]);
            int s2 = __ldg(&g_srcA[e0 + 2]), s3 = __ldg(&g_srcA[e0 + 3]);
            uint2 p0, p1, p2, p3;
            AGG_GATHER(p0, s0); AGG_GATHER(p1, s1); AGG_GATHER(p2, s2); AGG_GATHER(p3, s3);
            AGG_ACC(p0); AGG_ACC(p1); AGG_ACC(p2); AGG_ACC(p3);
        }
        // scalar remainder
        for (int e = e0 + (nf << 2); e < e1; e++) {
            int s0 = __ldg(&g_srcA[e]);
            uint2 r0;
            AGG_GATHER(r0, s0);
            AGG_ACC(r0);
        }
        float dv = g_dinv[node];
        ax *= dv; ay *= dv; az *= dv; aw *= dv;
        ((float4*)(out + (size_t)node * HH))[lane] = make_float4(ax, ay, az, aw);
        lsx += ax; lsy += ay; lsz += az; lsw += aw;
        lqx += ax * ax; lqy += ay * ay; lqz += az * az; lqw += aw * aw;
    }
    atomicAdd(&s_sum[col], lsx);     atomicAdd(&s_sum[col + 1], lsy);
    atomicAdd(&s_sum[col + 2], lsz); atomicAdd(&s_sum[col + 3], lsw);
    atomicAdd(&s_sq[col], lqx);      atomicAdd(&s_sq[col + 1], lqy);
    atomicAdd(&s_sq[col + 2], lqz);  atomicAdd(&s_sq[col + 3], lqw);
    __syncthreads();
    if (tid < HH) {
        atomicAdd(&g_stat[tid], s_sum[tid]);
        atomicAdd(&g_stat[HH + tid], s_sq[tid]);
    }
}

__global__ void k_fin(int layer) {  // finalize layer BN stats, re-zero g_stat
    int t = threadIdx.x;
    if (t < HH) {
        float m = g_stat[t] * (1.f / NN);
        float v = g_stat[HH + t] * (1.f / NN) - m * m;
        g_meanL[layer * HH + t] = m;
        g_istdL[layer * HH + t] = rsqrtf(v + EPSV);
        g_stat[t] = 0.f;
        g_stat[HH + t] = 0.f;
    }
}

// per-graph mean pool with fused BN+ReLU
__global__ void k_pool(const float* __restrict__ agg,
                       const float* __restrict__ gamma,
                       const float* __restrict__ beta, int layer) {
    int g = blockIdx.x, c = threadIdx.x;
    int b = g_goff[g], e = g_goff[g + 1];
    float is = g_istdL[layer * HH + c] * gamma[c];
    float sh = beta[c] - g_meanL[layer * HH + c] * is;
    float s = 0.f;
    for (int r = b; r < e; r++) {
        float x = agg[(size_t)r * HH + c];
        s += fmaxf(0.f, fmaf(x, is, sh));
    }
    int n = e - b;
    float cnt = (float)(n > 1 ? n : 1);
    g_pool[g * LH + layer * HH + c] = s / cnt;
}

// ---------------- MLP head ----------------
__global__ void k_lin1(const float* __restrict__ Wl1, const float* __restrict__ bl1) {
    __shared__ float sp[LH];
    int g = blockIdx.x, t = threadIdx.x;
    sp[t]       = g_pool[g * LH + t];
    sp[t + 128] = g_pool[g * LH + t + 128];
    sp[t + 256] = g_pool[g * LH + t + 256];
    __syncthreads();
    float a = bl1[t];
    #pragma unroll 4
    for (int k = 0; k < LH; k++) a = fmaf(sp[k], Wl1[k * HH + t], a);
    g_z[g * HH + t] = a;
}

__global__ void k_bn2() {
    int t = threadIdx.x;
    if (t < HH) {
        float s = 0.f, q = 0.f;
        for (int r = 0; r < GG; r++) {
            float x = g_z[r * HH + t];
            s += x; q += x * x;
        }
        float m = s * (1.f / GG);
        float v = q * (1.f / GG) - m * m;
        g_m2[t] = m;
        g_i2[t] = rsqrtf(v + EPSV);
    }
}

__global__ void k_final(const float* __restrict__ gl, const float* __restrict__ btl,
                        const float* __restrict__ Wl2, const float* __restrict__ bl2,
                        float* __restrict__ out) {
    __shared__ float zr[HH];
    __shared__ float lg[CC];
    __shared__ float s_ls;
    int g = blockIdx.x, t = threadIdx.x;
    float x = g_z[g * HH + t];
    zr[t] = fmaxf(0.f, (x - g_m2[t]) * g_i2[t] * gl[t] + btl[t]);
    __syncthreads();
    if (t < CC) {
        float d = bl2[t];
        #pragma unroll 4
        for (int j = 0; j < HH; j++) d = fmaf(zr[j], Wl2[j * CC + t], d);
        lg[t] = d;
    }
    __syncthreads();
    if (t == 0) {
        float m = lg[0];
        for (int c = 1; c < CC; c++) m = fmaxf(m, lg[c]);
        float se = 0.f;
        for (int c = 0; c < CC; c++) se += expf(lg[c] - m);
        s_ls = m + logf(se);
    }
    __syncthreads();
    if (t < CC) out[g * CC + t] = lg[t] - s_ls;
}

// ---------------- launch (single serial stream) ----------------
extern "C" void kernel_launch(void* const* d_in, const int* in_sizes, int n_in,
                              void* d_out, int out_size) {
    const float* x     = (const float*)d_in[0];
    const int*   ei    = (const int*)d_in[1];     // int32 (JAX x64 disabled)
    const int*   batch = (const int*)d_in[2];
    const float* W1  = (const float*)d_in[3];
    const float* g1  = (const float*)d_in[5];
    const float* bt1 = (const float*)d_in[6];
    const float* Wc  = (const float*)d_in[7];
    const float* gc  = (const float*)d_in[9];
    const float* btc = (const float*)d_in[10];
    const float* Wl1 = (const float*)d_in[11];
    const float* bl1 = (const float*)d_in[12];
    const float* gl  = (const float*)d_in[13];
    const float* btl = (const float*)d_in[14];
    const float* Wl2 = (const float*)d_in[15];
    const float* bl2 = (const float*)d_in[16];
    const int* src = ei;
    const int* dst = ei + EE;

    void *p_hW, *p_aggA, *p_aggB;
    cudaGetSymbolAddress(&p_hW, g_hW16);
    cudaGetSymbolAddress(&p_aggA, g_aggA);
    cudaGetSymbolAddress(&p_aggB, g_aggB);
    __half* hW  = (__half*)p_hW;
    float* aggA = (float*)p_aggA;
    float* aggB = (float*)p_aggB;

    const int GEMM_GRID = (NN + 127) / 128;
    const int AGG_GRID  = 1480;

    // ---- setup + layer-0 GEMM reordered so kernel #4 (profiled) is k_gemm_t ----
    k_count<<<(EE + 255) / 256, 256>>>(dst);          // 1
    s_partial<<<NBLK, 1024>>>();                      // 2 (writes dinv)
    s_add<<<NBLK, 1024>>>(batch);                     // 3
    k_gemm_t<<<GEMM_GRID, 256>>>(x, W1, hW, 0, 0, (const float*)0, (const float*)0); // 4 (profiled)
    k_fill<<<(EE + 255) / 256, 256>>>(src, dst);      // 5

    // ---- layer 0 ----
    k_agg<<<AGG_GRID, 256>>>(hW, aggA);
    k_fin<<<1, 128>>>(0);
    k_pool<<<GG, 128>>>(aggA, g1, bt1, 0);

    // ---- layer 1: BN0(aggA) -> aggB ----
    k_gemm_t<<<GEMM_GRID, 256>>>(aggA, Wc, hW, 1, 0, g1, bt1);
    k_agg<<<AGG_GRID, 256>>>(hW, aggB);
    k_fin<<<1, 128>>>(1);
    k_pool<<<GG, 128>>>(aggB, gc, btc, 1);

    // ---- layer 2: BN1(aggB) -> aggA ----
    k_gemm_t<<<GEMM_GRID, 256>>>(aggB, Wc + HH * HH, hW, 1, 1, gc, btc);
    k_agg<<<AGG_GRID, 256>>>(hW, aggA);
    k_fin<<<1, 128>>>(2);
    k_pool<<<GG, 128>>>(aggA, gc + HH, btc + HH, 2);

    // ---- head ----
    k_lin1<<<GG, 128>>>(Wl1, bl1);
    k_bn2<<<1, 128>>>();
    k_final<<<GG, 128>>>(gl, btl, Wl2, bl2, (float*)d_out);
}

// round 9
// speedup vs baseline: 1.2415x; 1.1448x over previous
#include <cuda_runtime.h>
#include <cuda_fp16.h>
#include <cstdint>

#define NN 100000
#define EE 1600000
#define HH 128
#define GG 512
#define CC 10
#define LH 384   // L*H
#define EPSV 1e-5f
#define NBLK 98  // ceil(NN/1024)

// ---------------- device scratch (no allocations allowed) ----------------
// zero-invariants: g_cnt, g_stat are zero at entry of every call
__device__ __align__(16) __half g_hW16[NN * HH]; // GEMM output, fp16 (dinv-scaled)
__device__ __align__(16) float g_aggA[NN * HH];  // aggregation ping (fp32)
__device__ __align__(16) float g_aggB[NN * HH];  // aggregation pong (fp32)
__device__ float g_dinv[NN];
__device__ int   g_cnt[NN];
__device__ int   g_off[NN + 1];
__device__ int   g_cursor[NN];
__device__ int   g_srcA[EE];
__device__ int   g_bsum[128];
__device__ float g_stat[2 * HH];       // [0:128) sum, [128:256) sumsq
__device__ float g_meanL[3 * HH];      // per-layer BN stats
__device__ float g_istdL[3 * HH];
__device__ int   g_goff[GG + 1];
__device__ float g_pool[GG * LH];
__device__ float g_z[GG * HH];
__device__ float g_m2[HH];
__device__ float g_i2[HH];

// ---------------- setup kernels ----------------
__global__ void k_count(const int* __restrict__ dst) {
    int e = blockIdx.x * blockDim.x + threadIdx.x;
    if (e < EE) atomicAdd(&g_cnt[dst[e]], 1);
}

// block-local exclusive scan + block sums; also writes dinv
__global__ void s_partial() {
    __shared__ int wsum[32];
    int tid = threadIdx.x, lane = tid & 31, wid = tid >> 5;
    int idx = blockIdx.x * 1024 + tid;
    int v = (idx < NN) ? g_cnt[idx] : 0;
    if (idx < NN) g_dinv[idx] = rsqrtf((float)(v + 1));
    int x = v;
    #pragma unroll
    for (int o = 1; o < 32; o <<= 1) {
        int y = __shfl_up_sync(0xffffffffu, x, o);
        if (lane >= o) x += y;
    }
    if (lane == 31) wsum[wid] = x;
    __syncthreads();
    if (wid == 0) {
        int w = wsum[lane];
        int xx = w;
        #pragma unroll
        for (int o = 1; o < 32; o <<= 1) {
            int y = __shfl_up_sync(0xffffffffu, xx, o);
            if (lane >= o) xx += y;
        }
        wsum[lane] = xx - w;
    }
    __syncthreads();
    int incl = x + wsum[wid];
    if (idx < NN) g_off[idx] = incl - v;     // block-local exclusive
    if (tid == 1023) g_bsum[blockIdx.x] = incl;
}

// finalize offsets, init cursor, zero g_cnt, graph offsets via boundary scan
__global__ void s_add(const int* __restrict__ batch) {
    __shared__ int sb[128];
    int tid = threadIdx.x;
    if (tid < 128) sb[tid] = (tid < NBLK) ? g_bsum[tid] : 0;
    __syncthreads();
    #pragma unroll
    for (int o = 1; o < 128; o <<= 1) {
        int v = 0;
        if (tid < 128 && tid >= o) v = sb[tid - o];
        __syncthreads();
        if (tid < 128) sb[tid] += v;
        __syncthreads();
    }
    int bpre = (blockIdx.x > 0) ? sb[blockIdx.x - 1] : 0;
    int idx = blockIdx.x * 1024 + tid;
    if (idx < NN) {
        int off = g_off[idx] + bpre;
        g_off[idx] = off;
        g_cursor[idx] = off;
        g_cnt[idx] = 0;                      // restore zero-invariant
        int b = batch[idx];
        int prev = (idx > 0) ? batch[idx - 1] : -1;
        for (int g = prev + 1; g <= b; g++) g_goff[g] = idx;
        if (idx == NN - 1)
            for (int g = b + 1; g <= GG; g++) g_goff[g] = NN;
    }
    if (idx == 0) g_off[NN] = EE;
}

__global__ void k_fill(const int* __restrict__ src, const int* __restrict__ dst) {
    int e = blockIdx.x * blockDim.x + threadIdx.x;
    if (e < EE) {
        int d = dst[e];
        int p = atomicAdd(&g_cursor[d], 1);
        g_srcA[p] = src[e];
    }
}

// ---------------- tf32 tensor-core GEMM (3xTF32 split) ----------------
__device__ __forceinline__ float tf32rn(float x) {
    uint32_t u;
    asm("cvt.rna.tf32.f32 %0, %1;" : "=r"(u) : "f"(x));
    return __uint_as_float(u);
}

__device__ __forceinline__ void mma_tf32(float& c0, float& c1, float& c2, float& c3,
                                         uint32_t a0, uint32_t a1, uint32_t a2, uint32_t a3,
                                         uint32_t b0, uint32_t b1) {
    asm volatile("mma.sync.aligned.m16n8k8.row.col.f32.tf32.tf32.f32 "
                 "{%0,%1,%2,%3},{%4,%5,%6,%7},{%8,%9},{%0,%1,%2,%3};"
                 : "+f"(c0), "+f"(c1), "+f"(c2), "+f"(c3)
                 : "r"(a0), "r"(a1), "r"(a2), "r"(a3), "r"(b0), "r"(b1));
}

#define AST 136  // smem stride: 136 mod 32 = 8 -> conflict-free fragment LDS

// C16[N,128] = fp16( dinv[row] * (relu(BN_layer(A))[N,128] @ W[128,128]) )
// 2 CTAs/SM forced; split-passes scheduled outermost for MMA ILP.
__global__ __launch_bounds__(256, 2) void k_gemm_t(const float* __restrict__ A,
                                                   const float* __restrict__ W,
                                                   __half* __restrict__ C16,
                                                   int doBN, int statLayer,
                                                   const float* __restrict__ gamma,
                                                   const float* __restrict__ beta) {
    __shared__ float sAhi[16][AST];
    __shared__ float sAlo[16][AST];
    __shared__ float sBhi[16][AST];
    __shared__ float sBlo[16][AST];
    __shared__ float sScale[HH], sShift[HH];

    int tid = threadIdx.x;
    if (doBN && tid < HH) {
        float is = g_istdL[statLayer * HH + tid] * gamma[tid];
        sScale[tid] = is;
        sShift[tid] = beta[tid] - g_meanL[statLayer * HH + tid] * is;
    }
    __syncthreads();

    int lane = tid & 31, wid = tid >> 5;
    int gid = lane >> 2, tig = lane & 3;
    int warp_m = wid & 3, warp_n = wid >> 2;     // 4 x 2 warp grid
    int mrow = warp_m * 32;
    int ncol0 = warp_n * 64;
    int rowBase = blockIdx.x * 128;

    float acc[2][8][4];
    #pragma unroll
    for (int mt = 0; mt < 2; mt++)
        #pragma unroll
        for (int nt = 0; nt < 8; nt++)
            #pragma unroll
            for (int r = 0; r < 4; r++) acc[mt][nt][r] = 0.f;

    for (int kc = 0; kc < 8; kc++) {
        int gcol = kc * 16;
        float4 av[2]; int arow[2], acol[2];
        #pragma unroll
        for (int i = 0; i < 2; i++) {
            int idx = i * 256 + tid;
            arow[i] = idx & 127;
            acol[i] = (idx >> 7) * 4;
            int gr = rowBase + arow[i];
            float4 v = make_float4(0.f, 0.f, 0.f, 0.f);
            if (gr < NN) v = *(const float4*)(A + (size_t)gr * HH + gcol + acol[i]);
            if (doBN) {
                int cb = gcol + acol[i];
                v.x = fmaxf(0.f, fmaf(v.x, sScale[cb], sShift[cb]));
                v.y = fmaxf(0.f, fmaf(v.y, sScale[cb + 1], sShift[cb + 1]));
                v.z = fmaxf(0.f, fmaf(v.z, sScale[cb + 2], sShift[cb + 2]));
                v.w = fmaxf(0.f, fmaf(v.w, sScale[cb + 3], sShift[cb + 3]));
            }
            av[i] = v;
        }
        float4 wv[2]; int wk[2], wc[2];
        #pragma unroll
        for (int i = 0; i < 2; i++) {
            int idx = i * 256 + tid;
            wk[i] = idx >> 5;
            wc[i] = (idx & 31) * 4;
            wv[i] = *(const float4*)(W + (size_t)(gcol + wk[i]) * HH + wc[i]);
        }
        __syncthreads();
        #pragma unroll
        for (int i = 0; i < 2; i++) {
            float vv[4] = {av[i].x, av[i].y, av[i].z, av[i].w};
            #pragma unroll
            for (int j = 0; j < 4; j++) {
                float hi = tf32rn(vv[j]);
                sAhi[acol[i] + j][arow[i]] = hi;
                sAlo[acol[i] + j][arow[i]] = tf32rn(vv[j] - hi);
            }
            float wvv[4] = {wv[i].x, wv[i].y, wv[i].z, wv[i].w};
            float h0 = tf32rn(wvv[0]), h1 = tf32rn(wvv[1]), h2 = tf32rn(wvv[2]), h3 = tf32rn(wvv[3]);
            *(float4*)&sBhi[wk[i]][wc[i]] = make_float4(h0, h1, h2, h3);
            *(float4*)&sBlo[wk[i]][wc[i]] = make_float4(tf32rn(wvv[0] - h0), tf32rn(wvv[1] - h1),
                                                        tf32rn(wvv[2] - h2), tf32rn(wvv[3] - h3));
        }
        __syncthreads();
        #pragma unroll
        for (int ks = 0; ks < 2; ks++) {
            int kb = ks * 8;
            uint32_t ahi[2][4], alo[2][4];
            #pragma unroll
            for (int mt = 0; mt < 2; mt++) {
                int m0 = mrow + mt * 16 + gid;
                ahi[mt][0] = __float_as_uint(sAhi[kb + tig][m0]);
                ahi[mt][1] = __float_as_uint(sAhi[kb + tig][m0 + 8]);
                ahi[mt][2] = __float_as_uint(sAhi[kb + tig + 4][m0]);
                ahi[mt][3] = __float_as_uint(sAhi[kb + tig + 4][m0 + 8]);
                alo[mt][0] = __float_as_uint(sAlo[kb + tig][m0]);
                alo[mt][1] = __float_as_uint(sAlo[kb + tig][m0 + 8]);
                alo[mt][2] = __float_as_uint(sAlo[kb + tig + 4][m0]);
                alo[mt][3] = __float_as_uint(sAlo[kb + tig + 4][m0 + 8]);
            }
            // pass 1: ahi * bhi  (16 independent MMAs)
            #pragma unroll
            for (int nt = 0; nt < 8; nt++) {
                int nc = ncol0 + nt * 8 + gid;
                uint32_t bh0 = __float_as_uint(sBhi[kb + tig][nc]);
                uint32_t bh1 = __float_as_uint(sBhi[kb + tig + 4][nc]);
                #pragma unroll
                for (int mt = 0; mt < 2; mt++) {
                    float* c = acc[mt][nt];
                    mma_tf32(c[0], c[1], c[2], c[3], ahi[mt][0], ahi[mt][1], ahi[mt][2], ahi[mt][3], bh0, bh1);
                }
            }
            // pass 2: alo * bhi
            #pragma unroll
            for (int nt = 0; nt < 8; nt++) {
                int nc = ncol0 + nt * 8 + gid;
                uint32_t bh0 = __float_as_uint(sBhi[kb + tig][nc]);
                uint32_t bh1 = __float_as_uint(sBhi[kb + tig + 4][nc]);
                #pragma unroll
                for (int mt = 0; mt < 2; mt++) {
                    float* c = acc[mt][nt];
                    mma_tf32(c[0], c[1], c[2], c[3], alo[mt][0], alo[mt][1], alo[mt][2], alo[mt][3], bh0, bh1);
                }
            }
            // pass 3: ahi * blo
            #pragma unroll
            for (int nt = 0; nt < 8; nt++) {
                int nc = ncol0 + nt * 8 + gid;
                uint32_t bl0 = __float_as_uint(sBlo[kb + tig][nc]);
                uint32_t bl1 = __float_as_uint(sBlo[kb + tig + 4][nc]);
                #pragma unroll
                for (int mt = 0; mt < 2; mt++) {
                    float* c = acc[mt][nt];
                    mma_tf32(c[0], c[1], c[2], c[3], ahi[mt][0], ahi[mt][1], ahi[mt][2], ahi[mt][3], bl0, bl1);
                }
            }
        }
        __syncthreads();
    }

    // epilogue: scale by dinv[row], convert fp16, write
    #pragma unroll
    for (int mt = 0; mt < 2; mt++) {
        int r0 = rowBase + mrow + mt * 16 + gid;
        int r1 = r0 + 8;
        float dv0 = (r0 < NN) ? g_dinv[r0] : 0.f;
        float dv1 = (r1 < NN) ? g_dinv[r1] : 0.f;
        #pragma unroll
        for (int nt = 0; nt < 8; nt++) {
            int c = ncol0 + nt * 8 + 2 * tig;
            float* a = acc[mt][nt];
            if (r0 < NN) *(__half2*)(C16 + (size_t)r0 * HH + c) = __floats2half2_rn(a[0] * dv0, a[1] * dv0);
            if (r1 < NN) *(__half2*)(C16 + (size_t)r1 * HH + c) = __floats2half2_rn(a[2] * dv1, a[3] * dv1);
        }
    }
}

// ---------------- aggregation: software-pipelined CSR gather + BN stats ----------------
// out[d] = dinv[d] * ( sum_{s in N(d)} hs[s] + hs[d] ),  hs = g_hW16 (dinv-scaled fp16)
#define AGG_GATHER(dst4, sidx) \
    { uint2 _r = *(const uint2*)(hw + (size_t)(sidx) * HH + col); dst4 = _r; }
#define AGG_ACC(r) \
    { float2 _a = __half22float2(*(__half2*)&(r).x); \
      float2 _b = __half22float2(*(__half2*)&(r).y); \
      ax += _a.x; ay += _a.y; az += _b.x; aw += _b.y; }

__global__ __launch_bounds__(256) void k_agg(const __half* __restrict__ hw,
                                             float* __restrict__ out) {
    __shared__ float s_sum[HH], s_sq[HH];
    int tid = threadIdx.x;
    if (tid < HH) { s_sum[tid] = 0.f; s_sq[tid] = 0.f; }
    __syncthreads();
    int lane = tid & 31;
    int col = lane * 4;   // 4 halves (= 1 uint2) per lane, 32 lanes = 128 cols
    int gw = (blockIdx.x * blockDim.x + tid) >> 5;
    int nw = (gridDim.x * blockDim.x) >> 5;
    float lsx = 0.f, lsy = 0.f, lsz = 0.f, lsw = 0.f;
    float lqx = 0.f, lqy = 0.f, lqz = 0.f, lqw = 0.f;
    for (int node = gw; node < NN; node += nw) {
        uint2 rv;
        AGG_GATHER(rv, node);
        float2 f0 = __half22float2(*(__half2*)&rv.x);
        float2 f1 = __half22float2(*(__half2*)&rv.y);
        float ax = f0.x, ay = f0.y, az = f1.x, aw = f1.y;
        int e0 = __ldg(&g_off[node]), e1 = __ldg(&g_off[node + 1]);
        int deg = e1 - e0;
        int nf = deg >> 2;             // number of full 4-edge groups
        if (nf >= 2) {
            int s0 = __ldg(&g_srcA[e0]),     s1 = __ldg(&g_srcA[e0 + 1]);
            int s2 = __ldg(&g_srcA[e0 + 2]), s3 = __ldg(&g_srcA[e0 + 3]);
            uint2 p0, p1, p2, p3;
            AGG_GATHER(p0, s0); AGG_GATHER(p1, s1); AGG_GATHER(p2, s2); AGG_GATHER(p3, s3);
            int t0 = __ldg(&g_srcA[e0 + 4]), t1 = __ldg(&g_srcA[e0 + 5]);
            int t2 = __ldg(&g_srcA[e0 + 6]), t3 = __ldg(&g_srcA[e0 + 7]);
            int e = e0 + 8;
            int iters = nf - 2;
            while (iters > 0) {
                uint2 q0, q1, q2, q3;
                AGG_GATHER(q0, t0); AGG_GATHER(q1, t1); AGG_GATHER(q2, t2); AGG_GATHER(q3, t3);
                t0 = __ldg(&g_srcA[e]);     t1 = __ldg(&g_srcA[e + 1]);
                t2 = __ldg(&g_srcA[e + 2]); t3 = __ldg(&g_srcA[e + 3]);
                AGG_ACC(p0); AGG_ACC(p1); AGG_ACC(p2); AGG_ACC(p3);
                p0 = q0; p1 = q1; p2 = q2; p3 = q3;
                e += 4; iters--;
            }
            uint2 q0, q1, q2, q3;
            AGG_GATHER(q0, t0); AGG_GATHER(q1, t1); AGG_GATHER(q2, t2); AGG_GATHER(q3, t3);
            AGG_ACC(p0); AGG_ACC(p1); AGG_ACC(p2); AGG_ACC(p3);
            AGG_ACC(q0); AGG_ACC(q1); AGG_ACC(q2); AGG_ACC(q3);
        } else if (nf == 1) {
            int s0 = __ldg(&g_srcA[e0]),     s1 = __ldg(&g_srcA[e0 + 1]);
            int s2 = __ldg(&g_srcA[e0 + 2]), s3 = __ldg(&g_srcA[e0 + 3]);
            uint2 p0, p1, p2, p3;
            AGG_GATHER(p0, s0); AGG_GATHER(p1, s1); AGG_GATHER(p2, s2); AGG_GATHER(p3, s3);
            AGG_ACC(p0); AGG_ACC(p1); AGG_ACC(p2); AGG_ACC(p3);
        }
        for (int e = e0 + (nf << 2); e < e1; e++) {
            int s0 = __ldg(&g_srcA[e]);
            uint2 r0;
            AGG_GATHER(r0, s0);
            AGG_ACC(r0);
        }
        float dv = g_dinv[node];
        ax *= dv; ay *= dv; az *= dv; aw *= dv;
        ((float4*)(out + (size_t)node * HH))[lane] = make_float4(ax, ay, az, aw);
        lsx += ax; lsy += ay; lsz += az; lsw += aw;
        lqx += ax * ax; lqy += ay * ay; lqz += az * az; lqw += aw * aw;
    }
    atomicAdd(&s_sum[col], lsx);     atomicAdd(&s_sum[col + 1], lsy);
    atomicAdd(&s_sum[col + 2], lsz); atomicAdd(&s_sum[col + 3], lsw);
    atomicAdd(&s_sq[col], lqx);      atomicAdd(&s_sq[col + 1], lqy);
    atomicAdd(&s_sq[col + 2], lqz);  atomicAdd(&s_sq[col + 3], lqw);
    __syncthreads();
    if (tid < HH) {
        atomicAdd(&g_stat[tid], s_sum[tid]);
        atomicAdd(&g_stat[HH + tid], s_sq[tid]);
    }
}

__global__ void k_fin(int layer) {  // finalize layer BN stats, re-zero g_stat
    int t = threadIdx.x;
    if (t < HH) {
        float m = g_stat[t] * (1.f / NN);
        float v = g_stat[HH + t] * (1.f / NN) - m * m;
        g_meanL[layer * HH + t] = m;
        g_istdL[layer * HH + t] = rsqrtf(v + EPSV);
        g_stat[t] = 0.f;
        g_stat[HH + t] = 0.f;
    }
}

// per-graph mean pool with fused BN+ReLU
__global__ void k_pool(const float* __restrict__ agg,
                       const float* __restrict__ gamma,
                       const float* __restrict__ beta, int layer) {
    int g = blockIdx.x, c = threadIdx.x;
    int b = g_goff[g], e = g_goff[g + 1];
    float is = g_istdL[layer * HH + c] * gamma[c];
    float sh = beta[c] - g_meanL[layer * HH + c] * is;
    float s = 0.f;
    for (int r = b; r < e; r++) {
        float x = agg[(size_t)r * HH + c];
        s += fmaxf(0.f, fmaf(x, is, sh));
    }
    int n = e - b;
    float cnt = (float)(n > 1 ? n : 1);
    g_pool[g * LH + layer * HH + c] = s / cnt;
}

// ---------------- MLP head ----------------
__global__ void k_lin1(const float* __restrict__ Wl1, const float* __restrict__ bl1) {
    __shared__ float sp[LH];
    int g = blockIdx.x, t = threadIdx.x;
    sp[t]       = g_pool[g * LH + t];
    sp[t + 128] = g_pool[g * LH + t + 128];
    sp[t + 256] = g_pool[g * LH + t + 256];
    __syncthreads();
    float a = bl1[t];
    #pragma unroll 4
    for (int k = 0; k < LH; k++) a = fmaf(sp[k], Wl1[k * HH + t], a);
    g_z[g * HH + t] = a;
}

__global__ void k_bn2() {
    int t = threadIdx.x;
    if (t < HH) {
        float s = 0.f, q = 0.f;
        for (int r = 0; r < GG; r++) {
            float x = g_z[r * HH + t];
            s += x; q += x * x;
        }
        float m = s * (1.f / GG);
        float v = q * (1.f / GG) - m * m;
        g_m2[t] = m;
        g_i2[t] = rsqrtf(v + EPSV);
    }
}

__global__ void k_final(const float* __restrict__ gl, const float* __restrict__ btl,
                        const float* __restrict__ Wl2, const float* __restrict__ bl2,
                        float* __restrict__ out) {
    __shared__ float zr[HH];
    __shared__ float lg[CC];
    __shared__ float s_ls;
    int g = blockIdx.x, t = threadIdx.x;
    float x = g_z[g * HH + t];
    zr[t] = fmaxf(0.f, (x - g_m2[t]) * g_i2[t] * gl[t] + btl[t]);
    __syncthreads();
    if (t < CC) {
        float d = bl2[t];
        #pragma unroll 4
        for (int j = 0; j < HH; j++) d = fmaf(zr[j], Wl2[j * CC + t], d);
        lg[t] = d;
    }
    __syncthreads();
    if (t == 0) {
        float m = lg[0];
        for (int c = 1; c < CC; c++) m = fmaxf(m, lg[c]);
        float se = 0.f;
        for (int c = 0; c < CC; c++) se += expf(lg[c] - m);
        s_ls = m + logf(se);
    }
    __syncthreads();
    if (t < CC) out[g * CC + t] = lg[t] - s_ls;
}

// ---------------- launch (single serial stream) ----------------
extern "C" void kernel_launch(void* const* d_in, const int* in_sizes, int n_in,
                              void* d_out, int out_size) {
    const float* x     = (const float*)d_in[0];
    const int*   ei    = (const int*)d_in[1];     // int32 (JAX x64 disabled)
    const int*   batch = (const int*)d_in[2];
    const float* W1  = (const float*)d_in[3];
    const float* g1  = (const float*)d_in[5];
    const float* bt1 = (const float*)d_in[6];
    const float* Wc  = (const float*)d_in[7];
    const float* gc  = (const float*)d_in[9];
    const float* btc = (const float*)d_in[10];
    const float* Wl1 = (const float*)d_in[11];
    const float* bl1 = (const float*)d_in[12];
    const float* gl  = (const float*)d_in[13];
    const float* btl = (const float*)d_in[14];
    const float* Wl2 = (const float*)d_in[15];
    const float* bl2 = (const float*)d_in[16];
    const int* src = ei;
    const int* dst = ei + EE;

    void *p_hW, *p_aggA, *p_aggB;
    cudaGetSymbolAddress(&p_hW, g_hW16);
    cudaGetSymbolAddress(&p_aggA, g_aggA);
    cudaGetSymbolAddress(&p_aggB, g_aggB);
    __half* hW  = (__half*)p_hW;
    float* aggA = (float*)p_aggA;
    float* aggB = (float*)p_aggB;

    const int GEMM_GRID = (NN + 127) / 128;
    const int AGG_GRID  = 1480;

    // ---- setup; kernel #4 (profiled) is k_gemm_t ----
    k_count<<<(EE + 255) / 256, 256>>>(dst);          // 1
    s_partial<<<NBLK, 1024>>>();                      // 2 (writes dinv)
    s_add<<<NBLK, 1024>>>(batch);                     // 3
    k_gemm_t<<<GEMM_GRID, 256>>>(x, W1, hW, 0, 0, (const float*)0, (const float*)0); // 4 (profiled)
    k_fill<<<(EE + 255) / 256, 256>>>(src, dst);      // 5

    // ---- layer 0 ----
    k_agg<<<AGG_GRID, 256>>>(hW, aggA);
    k_fin<<<1, 128>>>(0);
    k_pool<<<GG, 128>>>(aggA, g1, bt1, 0);

    // ---- layer 1: BN0(aggA) -> aggB ----
    k_gemm_t<<<GEMM_GRID, 256>>>(aggA, Wc, hW, 1, 0, g1, bt1);
    k_agg<<<AGG_GRID, 256>>>(hW, aggB);
    k_fin<<<1, 128>>>(1);
    k_pool<<<GG, 128>>>(aggB, gc, btc, 1);

    // ---- layer 2: BN1(aggB) -> aggA ----
    k_gemm_t<<<GEMM_GRID, 256>>>(aggB, Wc + HH * HH, hW, 1, 1, gc, btc);
    k_agg<<<AGG_GRID, 256>>>(hW, aggA);
    k_fin<<<1, 128>>>(2);
    k_pool<<<GG, 128>>>(aggA, gc + HH, btc + HH, 2);

    // ---- head ----
    k_lin1<<<GG, 128>>>(Wl1, bl1);
    k_bn2<<<1, 128>>>();
    k_final<<<GG, 128>>>(gl, btl, Wl2, bl2, (float*)d_out);
}

// round 10
// speedup vs baseline: 1.5340x; 1.2356x over previous
#include <cuda_runtime.h>
#include <cuda_fp16.h>
#include <cstdint>

#define NN 100000
#define EE 1600000
#define HH 128
#define GG 512
#define CC 10
#define LH 384   // L*H
#define EPSV 1e-5f
#define NBLK 98  // ceil(NN/1024)

// ---------------- device scratch (no allocations allowed) ----------------
// zero-invariants: g_cnt, g_stat are zero at entry of every call
__device__ __align__(16) __half g_hW16[NN * HH]; // GEMM output, fp16 (dinv-scaled)
__device__ __align__(16) float g_aggA[NN * HH];  // aggregation ping (fp32)
__device__ __align__(16) float g_aggB[NN * HH];  // aggregation pong (fp32)
__device__ float g_dinv[NN];
__device__ int   g_cnt[NN];
__device__ int   g_off[NN + 1];
__device__ int   g_cursor[NN];
__device__ int   g_srcA[EE];
__device__ int   g_bsum[128];
__device__ float g_stat[2 * HH];       // [0:128) sum, [128:256) sumsq
__device__ float g_meanL[3 * HH];      // per-layer BN stats
__device__ float g_istdL[3 * HH];
__device__ int   g_goff[GG + 1];
__device__ float g_pool[GG * LH];
__device__ float g_z[GG * HH];
__device__ float g_m2[HH];
__device__ float g_i2[HH];

// ---------------- setup kernels ----------------
__global__ void k_count(const int* __restrict__ dst) {
    int e = blockIdx.x * blockDim.x + threadIdx.x;
    if (e < EE) atomicAdd(&g_cnt[dst[e]], 1);
}

// block-local exclusive scan + block sums; also writes dinv
__global__ void s_partial() {
    __shared__ int wsum[32];
    int tid = threadIdx.x, lane = tid & 31, wid = tid >> 5;
    int idx = blockIdx.x * 1024 + tid;
    int v = (idx < NN) ? g_cnt[idx] : 0;
    if (idx < NN) g_dinv[idx] = rsqrtf((float)(v + 1));
    int x = v;
    #pragma unroll
    for (int o = 1; o < 32; o <<= 1) {
        int y = __shfl_up_sync(0xffffffffu, x, o);
        if (lane >= o) x += y;
    }
    if (lane == 31) wsum[wid] = x;
    __syncthreads();
    if (wid == 0) {
        int w = wsum[lane];
        int xx = w;
        #pragma unroll
        for (int o = 1; o < 32; o <<= 1) {
            int y = __shfl_up_sync(0xffffffffu, xx, o);
            if (lane >= o) xx += y;
        }
        wsum[lane] = xx - w;
    }
    __syncthreads();
    int incl = x + wsum[wid];
    if (idx < NN) g_off[idx] = incl - v;     // block-local exclusive
    if (tid == 1023) g_bsum[blockIdx.x] = incl;
}

// finalize offsets, init cursor, zero g_cnt, graph offsets via boundary scan
__global__ void s_add(const int* __restrict__ batch) {
    __shared__ int sb[128];
    int tid = threadIdx.x;
    if (tid < 128) sb[tid] = (tid < NBLK) ? g_bsum[tid] : 0;
    __syncthreads();
    #pragma unroll
    for (int o = 1; o < 128; o <<= 1) {
        int v = 0;
        if (tid < 128 && tid >= o) v = sb[tid - o];
        __syncthreads();
        if (tid < 128) sb[tid] += v;
        __syncthreads();
    }
    int bpre = (blockIdx.x > 0) ? sb[blockIdx.x - 1] : 0;
    int idx = blockIdx.x * 1024 + tid;
    if (idx < NN) {
        int off = g_off[idx] + bpre;
        g_off[idx] = off;
        g_cursor[idx] = off;
        g_cnt[idx] = 0;                      // restore zero-invariant
        int b = batch[idx];
        int prev = (idx > 0) ? batch[idx - 1] : -1;
        for (int g = prev + 1; g <= b; g++) g_goff[g] = idx;
        if (idx == NN - 1)
            for (int g = b + 1; g <= GG; g++) g_goff[g] = NN;
    }
    if (idx == 0) g_off[NN] = EE;
}

__global__ void k_fill(const int* __restrict__ src, const int* __restrict__ dst) {
    int e = blockIdx.x * blockDim.x + threadIdx.x;
    if (e < EE) {
        int d = dst[e];
        int p = atomicAdd(&g_cursor[d], 1);
        g_srcA[p] = src[e];
    }
}

// ---------------- fp16 tensor-core GEMM (m16n8k16, fp32 accumulate) ----------------
__device__ __forceinline__ void mma_f16(float& c0, float& c1, float& c2, float& c3,
                                        uint32_t a0, uint32_t a1, uint32_t a2, uint32_t a3,
                                        uint32_t b0, uint32_t b1) {
    asm volatile("mma.sync.aligned.m16n8k16.row.col.f32.f16.f16.f32 "
                 "{%0,%1,%2,%3},{%4,%5,%6,%7},{%8,%9},{%0,%1,%2,%3};"
                 : "+f"(c0), "+f"(c1), "+f"(c2), "+f"(c3)
                 : "r"(a0), "r"(a1), "r"(a2), "r"(a3), "r"(b0), "r"(b1));
}

#define HPAD 18  // halves per smem row: stride 36B, addr/4 step 9 (odd) -> conflict-free

// C16[N,128] = fp16( dinv[row] * (relu(BN_layer(A))[N,128] @ W[128,128]) )
__global__ __launch_bounds__(256, 2) void k_gemm_h(const float* __restrict__ A,
                                                   const float* __restrict__ W,
                                                   __half* __restrict__ C16,
                                                   int doBN, int statLayer,
                                                   const float* __restrict__ gamma,
                                                   const float* __restrict__ beta) {
    __shared__ __align__(16) __half sA[128][HPAD];  // [row][k]
    __shared__ __align__(16) __half sB[128][HPAD];  // [n][k]  (transposed W chunk)
    __shared__ float sScale[HH], sShift[HH];

    int tid = threadIdx.x;
    if (doBN && tid < HH) {
        float is = g_istdL[statLayer * HH + tid] * gamma[tid];
        sScale[tid] = is;
        sShift[tid] = beta[tid] - g_meanL[statLayer * HH + tid] * is;
    }
    __syncthreads();

    int lane = tid & 31, wid = tid >> 5;
    int gid = lane >> 2, tig = lane & 3;
    int warp_m = wid & 3, warp_n = wid >> 2;     // 4 x 2 warp grid
    int mrow = warp_m * 32;
    int ncol0 = warp_n * 64;
    int rowBase = blockIdx.x * 128;

    float acc[2][8][4];
    #pragma unroll
    for (int mt = 0; mt < 2; mt++)
        #pragma unroll
        for (int nt = 0; nt < 8; nt++)
            #pragma unroll
            for (int r = 0; r < 4; r++) acc[mt][nt][r] = 0.f;

    for (int kc = 0; kc < 8; kc++) {
        int gcol = kc * 16;
        // stage A chunk [128 rows x 16 k] (BN+ReLU fused), fp16
        #pragma unroll
        for (int i = 0; i < 2; i++) {
            int idx = i * 256 + tid;
            int row = idx & 127;
            int k0 = (idx >> 7) * 4;     // 0,4,8,12
            int gr = rowBase + row;
            float4 v = make_float4(0.f, 0.f, 0.f, 0.f);
            if (gr < NN) v = *(const float4*)(A + (size_t)gr * HH + gcol + k0);
            if (doBN) {
                int cb = gcol + k0;
                v.x = fmaxf(0.f, fmaf(v.x, sScale[cb], sShift[cb]));
                v.y = fmaxf(0.f, fmaf(v.y, sScale[cb + 1], sShift[cb + 1]));
                v.z = fmaxf(0.f, fmaf(v.z, sScale[cb + 2], sShift[cb + 2]));
                v.w = fmaxf(0.f, fmaf(v.w, sScale[cb + 3], sShift[cb + 3]));
            }
            *(__half2*)&sA[row][k0]     = __floats2half2_rn(v.x, v.y);
            *(__half2*)&sA[row][k0 + 2] = __floats2half2_rn(v.z, v.w);
        }
        // stage B chunk transposed: sB[n][k], column reads of W (coalesced across n)
        #pragma unroll
        for (int i = 0; i < 2; i++) {
            int idx = i * 256 + tid;
            int n  = idx & 127;
            int k0 = (idx >> 7) * 4;
            float w0 = W[(size_t)(gcol + k0)     * HH + n];
            float w1 = W[(size_t)(gcol + k0 + 1) * HH + n];
            float w2 = W[(size_t)(gcol + k0 + 2) * HH + n];
            float w3 = W[(size_t)(gcol + k0 + 3) * HH + n];
            *(__half2*)&sB[n][k0]     = __floats2half2_rn(w0, w1);
            *(__half2*)&sB[n][k0 + 2] = __floats2half2_rn(w2, w3);
        }
        __syncthreads();

        // fragments + 16 independent MMAs per warp (full k16 per chunk)
        uint32_t a[2][4];
        #pragma unroll
        for (int mt = 0; mt < 2; mt++) {
            int m0 = mrow + mt * 16 + gid;
            a[mt][0] = *(const uint32_t*)&sA[m0][2 * tig];
            a[mt][1] = *(const uint32_t*)&sA[m0 + 8][2 * tig];
            a[mt][2] = *(const uint32_t*)&sA[m0][2 * tig + 8];
            a[mt][3] = *(const uint32_t*)&sA[m0 + 8][2 * tig + 8];
        }
        #pragma unroll
        for (int nt = 0; nt < 8; nt++) {
            int nc = ncol0 + nt * 8 + gid;
            uint32_t b0 = *(const uint32_t*)&sB[nc][2 * tig];
            uint32_t b1 = *(const uint32_t*)&sB[nc][2 * tig + 8];
            #pragma unroll
            for (int mt = 0; mt < 2; mt++) {
                float* c = acc[mt][nt];
                mma_f16(c[0], c[1], c[2], c[3],
                        a[mt][0], a[mt][1], a[mt][2], a[mt][3], b0, b1);
            }
        }
        __syncthreads();
    }

    // epilogue: scale by dinv[row], convert fp16, write (C layout same as tf32 ver.)
    #pragma unroll
    for (int mt = 0; mt < 2; mt++) {
        int r0 = rowBase + mrow + mt * 16 + gid;
        int r1 = r0 + 8;
        float dv0 = (r0 < NN) ? g_dinv[r0] : 0.f;
        float dv1 = (r1 < NN) ? g_dinv[r1] : 0.f;
        #pragma unroll
        for (int nt = 0; nt < 8; nt++) {
            int c = ncol0 + nt * 8 + 2 * tig;
            float* a2 = acc[mt][nt];
            if (r0 < NN) *(__half2*)(C16 + (size_t)r0 * HH + c) = __floats2half2_rn(a2[0] * dv0, a2[1] * dv0);
            if (r1 < NN) *(__half2*)(C16 + (size_t)r1 * HH + c) = __floats2half2_rn(a2[2] * dv1, a2[3] * dv1);
        }
    }
}

// ---------------- aggregation: software-pipelined CSR gather + BN stats ----------------
// out[d] = dinv[d] * ( sum_{s in N(d)} hs[s] + hs[d] ),  hs = g_hW16 (dinv-scaled fp16)
#define AGG_GATHER(dst4, sidx) \
    { uint2 _r = *(const uint2*)(hw + (size_t)(sidx) * HH + col); dst4 = _r; }
#define AGG_ACC(r) \
    { float2 _a = __half22float2(*(__half2*)&(r).x); \
      float2 _b = __half22float2(*(__half2*)&(r).y); \
      ax += _a.x; ay += _a.y; az += _b.x; aw += _b.y; }

__global__ __launch_bounds__(256) void k_agg(const __half* __restrict__ hw,
                                             float* __restrict__ out) {
    __shared__ float s_sum[HH], s_sq[HH];
    int tid = threadIdx.x;
    if (tid < HH) { s_sum[tid] = 0.f; s_sq[tid] = 0.f; }
    __syncthreads();
    int lane = tid & 31;
    int col = lane * 4;   // 4 halves (= 1 uint2) per lane, 32 lanes = 128 cols
    int gw = (blockIdx.x * blockDim.x + tid) >> 5;
    int nw = (gridDim.x * blockDim.x) >> 5;
    float lsx = 0.f, lsy = 0.f, lsz = 0.f, lsw = 0.f;
    float lqx = 0.f, lqy = 0.f, lqz = 0.f, lqw = 0.f;
    for (int node = gw; node < NN; node += nw) {
        uint2 rv;
        AGG_GATHER(rv, node);
        float2 f0 = __half22float2(*(__half2*)&rv.x);
        float2 f1 = __half22float2(*(__half2*)&rv.y);
        float ax = f0.x, ay = f0.y, az = f1.x, aw = f1.y;
        int e0 = __ldg(&g_off[node]), e1 = __ldg(&g_off[node + 1]);
        int deg = e1 - e0;
        int nf = deg >> 2;             // number of full 4-edge groups
        if (nf >= 2) {
            int s0 = __ldg(&g_srcA[e0]),     s1 = __ldg(&g_srcA[e0 + 1]);
            int s2 = __ldg(&g_srcA[e0 + 2]), s3 = __ldg(&g_srcA[e0 + 3]);
            uint2 p0, p1, p2, p3;
            AGG_GATHER(p0, s0); AGG_GATHER(p1, s1); AGG_GATHER(p2, s2); AGG_GATHER(p3, s3);
            int t0 = __ldg(&g_srcA[e0 + 4]), t1 = __ldg(&g_srcA[e0 + 5]);
            int t2 = __ldg(&g_srcA[e0 + 6]), t3 = __ldg(&g_srcA[e0 + 7]);
            int e = e0 + 8;
            int iters = nf - 2;
            while (iters > 0) {
                uint2 q0, q1, q2, q3;
                AGG_GATHER(q0, t0); AGG_GATHER(q1, t1); AGG_GATHER(q2, t2); AGG_GATHER(q3, t3);
                t0 = __ldg(&g_srcA[e]);     t1 = __ldg(&g_srcA[e + 1]);
                t2 = __ldg(&g_srcA[e + 2]); t3 = __ldg(&g_srcA[e + 3]);
                AGG_ACC(p0); AGG_ACC(p1); AGG_ACC(p2); AGG_ACC(p3);
                p0 = q0; p1 = q1; p2 = q2; p3 = q3;
                e += 4; iters--;
            }
            uint2 q0, q1, q2, q3;
            AGG_GATHER(q0, t0); AGG_GATHER(q1, t1); AGG_GATHER(q2, t2); AGG_GATHER(q3, t3);
            AGG_ACC(p0); AGG_ACC(p1); AGG_ACC(p2); AGG_ACC(p3);
            AGG_ACC(q0); AGG_ACC(q1); AGG_ACC(q2); AGG_ACC(q3);
        } else if (nf == 1) {
            int s0 = __ldg(&g_srcA[e0]),     s1 = __ldg(&g_srcA[e0 + 1]);
            int s2 = __ldg(&g_srcA[e0 + 2]), s3 = __ldg(&g_srcA[e0 + 3]);
            uint2 p0, p1, p2, p3;
            AGG_GATHER(p0, s0); AGG_GATHER(p1, s1); AGG_GATHER(p2, s2); AGG_GATHER(p3, s3);
            AGG_ACC(p0); AGG_ACC(p1); AGG_ACC(p2); AGG_ACC(p3);
        }
        for (int e = e0 + (nf << 2); e < e1; e++) {
            int s0 = __ldg(&g_srcA[e]);
            uint2 r0;
            AGG_GATHER(r0, s0);
            AGG_ACC(r0);
        }
        float dv = g_dinv[node];
        ax *= dv; ay *= dv; az *= dv; aw *= dv;
        ((float4*)(out + (size_t)node * HH))[lane] = make_float4(ax, ay, az, aw);
        lsx += ax; lsy += ay; lsz += az; lsw += aw;
        lqx += ax * ax; lqy += ay * ay; lqz += az * az; lqw += aw * aw;
    }
    atomicAdd(&s_sum[col], lsx);     atomicAdd(&s_sum[col + 1], lsy);
    atomicAdd(&s_sum[col + 2], lsz); atomicAdd(&s_sum[col + 3], lsw);
    atomicAdd(&s_sq[col], lqx);      atomicAdd(&s_sq[col + 1], lqy);
    atomicAdd(&s_sq[col + 2], lqz);  atomicAdd(&s_sq[col + 3], lqw);
    __syncthreads();
    if (tid < HH) {
        atomicAdd(&g_stat[tid], s_sum[tid]);
        atomicAdd(&g_stat[HH + tid], s_sq[tid]);
    }
}

__global__ void k_fin(int layer) {  // finalize layer BN stats, re-zero g_stat
    int t = threadIdx.x;
    if (t < HH) {
        float m = g_stat[t] * (1.f / NN);
        float v = g_stat[HH + t] * (1.f / NN) - m * m;
        g_meanL[layer * HH + t] = m;
        g_istdL[layer * HH + t] = rsqrtf(v + EPSV);
        g_stat[t] = 0.f;
        g_stat[HH + t] = 0.f;
    }
}

// per-graph mean pool with fused BN+ReLU
__global__ void k_pool(const float* __restrict__ agg,
                       const float* __restrict__ gamma,
                       const float* __restrict__ beta, int layer) {
    int g = blockIdx.x, c = threadIdx.x;
    int b = g_goff[g], e = g_goff[g + 1];
    float is = g_istdL[layer * HH + c] * gamma[c];
    float sh = beta[c] - g_meanL[layer * HH + c] * is;
    float s = 0.f;
    for (int r = b; r < e; r++) {
        float x = agg[(size_t)r * HH + c];
        s += fmaxf(0.f, fmaf(x, is, sh));
    }
    int n = e - b;
    float cnt = (float)(n > 1 ? n : 1);
    g_pool[g * LH + layer * HH + c] = s / cnt;
}

// ---------------- MLP head ----------------
__global__ void k_lin1(const float* __restrict__ Wl1, const float* __restrict__ bl1) {
    __shared__ float sp[LH];
    int g = blockIdx.x, t = threadIdx.x;
    sp[t]       = g_pool[g * LH + t];
    sp[t + 128] = g_pool[g * LH + t + 128];
    sp[t + 256] = g_pool[g * LH + t + 256];
    __syncthreads();
    float a = bl1[t];
    #pragma unroll 4
    for (int k = 0; k < LH; k++) a = fmaf(sp[k], Wl1[k * HH + t], a);
    g_z[g * HH + t] = a;
}

__global__ void k_bn2() {
    int t = threadIdx.x;
    if (t < HH) {
        float s = 0.f, q = 0.f;
        for (int r = 0; r < GG; r++) {
            float x = g_z[r * HH + t];
            s += x; q += x * x;
        }
        float m = s * (1.f / GG);
        float v = q * (1.f / GG) - m * m;
        g_m2[t] = m;
        g_i2[t] = rsqrtf(v + EPSV);
    }
}

__global__ void k_final(const float* __restrict__ gl, const float* __restrict__ btl,
                        const float* __restrict__ Wl2, const float* __restrict__ bl2,
                        float* __restrict__ out) {
    __shared__ float zr[HH];
    __shared__ float lg[CC];
    __shared__ float s_ls;
    int g = blockIdx.x, t = threadIdx.x;
    float x = g_z[g * HH + t];
    zr[t] = fmaxf(0.f, (x - g_m2[t]) * g_i2[t] * gl[t] + btl[t]);
    __syncthreads();
    if (t < CC) {
        float d = bl2[t];
        #pragma unroll 4
        for (int j = 0; j < HH; j++) d = fmaf(zr[j], Wl2[j * CC + t], d);
        lg[t] = d;
    }
    __syncthreads();
    if (t == 0) {
        float m = lg[0];
        for (int c = 1; c < CC; c++) m = fmaxf(m, lg[c]);
        float se = 0.f;
        for (int c = 0; c < CC; c++) se += expf(lg[c] - m);
        s_ls = m + logf(se);
    }
    __syncthreads();
    if (t < CC) out[g * CC + t] = lg[t] - s_ls;
}

// ---------------- launch (single serial stream) ----------------
extern "C" void kernel_launch(void* const* d_in, const int* in_sizes, int n_in,
                              void* d_out, int out_size) {
    const float* x     = (const float*)d_in[0];
    const int*   ei    = (const int*)d_in[1];     // int32 (JAX x64 disabled)
    const int*   batch = (const int*)d_in[2];
    const float* W1  = (const float*)d_in[3];
    const float* g1  = (const float*)d_in[5];
    const float* bt1 = (const float*)d_in[6];
    const float* Wc  = (const float*)d_in[7];
    const float* gc  = (const float*)d_in[9];
    const float* btc = (const float*)d_in[10];
    const float* Wl1 = (const float*)d_in[11];
    const float* bl1 = (const float*)d_in[12];
    const float* gl  = (const float*)d_in[13];
    const float* btl = (const float*)d_in[14];
    const float* Wl2 = (const float*)d_in[15];
    const float* bl2 = (const float*)d_in[16];
    const int* src = ei;
    const int* dst = ei + EE;

    void *p_hW, *p_aggA, *p_aggB;
    cudaGetSymbolAddress(&p_hW, g_hW16);
    cudaGetSymbolAddress(&p_aggA, g_aggA);
    cudaGetSymbolAddress(&p_aggB, g_aggB);
    __half* hW  = (__half*)p_hW;
    float* aggA = (float*)p_aggA;
    float* aggB = (float*)p_aggB;

    const int GEMM_GRID = (NN + 127) / 128;
    const int AGG_GRID  = 1480;

    // ---- setup; kernel #4 (profiled) is k_gemm_h ----
    k_count<<<(EE + 255) / 256, 256>>>(dst);          // 1
    s_partial<<<NBLK, 1024>>>();                      // 2 (writes dinv)
    s_add<<<NBLK, 1024>>>(batch);                     // 3
    k_gemm_h<<<GEMM_GRID, 256>>>(x, W1, hW, 0, 0, (const float*)0, (const float*)0); // 4 (profiled)
    k_fill<<<(EE + 255) / 256, 256>>>(src, dst);      // 5

    // ---- layer 0 ----
    k_agg<<<AGG_GRID, 256>>>(hW, aggA);
    k_fin<<<1, 128>>>(0);
    k_pool<<<GG, 128>>>(aggA, g1, bt1, 0);

    // ---- layer 1: BN0(aggA) -> aggB ----
    k_gemm_h<<<GEMM_GRID, 256>>>(aggA, Wc, hW, 1, 0, g1, bt1);
    k_agg<<<AGG_GRID, 256>>>(hW, aggB);
    k_fin<<<1, 128>>>(1);
    k_pool<<<GG, 128>>>(aggB, gc, btc, 1);

    // ---- layer 2: BN1(aggB) -> aggA ----
    k_gemm_h<<<GEMM_GRID, 256>>>(aggB, Wc + HH * HH, hW, 1, 1, gc, btc);
    k_agg<<<AGG_GRID, 256>>>(hW, aggA);
    k_fin<<<1, 128>>>(2);
    k_pool<<<GG, 128>>>(aggA, gc + HH, btc + HH, 2);

    // ---- head ----
    k_lin1<<<GG, 128>>>(Wl1, bl1);
    k_bn2<<<1, 128>>>();
    k_final<<<GG, 128>>>(gl, btl, Wl2, bl2, (float*)d_out);
}

// round 12
// speedup vs baseline: 1.6976x; 1.1066x over previous
#include <cuda_runtime.h>
#include <cuda_fp16.h>
#include <cstdint>

#define NN 100000
#define EE 1600000
#define HH 128
#define GG 512
#define CC 10
#define LH 384   // L*H
#define EPSV 1e-5f
#define NBLK 98  // ceil(NN/1024)

// ---------------- device scratch (no allocations allowed) ----------------
// zero-invariants: g_cnt, g_stat are zero at entry of every call
__device__ __align__(16) __half g_hW16[NN * HH]; // GEMM output, fp16 (dinv-scaled)
__device__ __align__(16) __half g_aggA[NN * HH]; // aggregation ping (fp16)
__device__ __align__(16) __half g_aggB[NN * HH]; // aggregation pong (fp16)
__device__ float g_dinv[NN];
__device__ int   g_cnt[NN];
__device__ int   g_off[NN + 1];
__device__ int   g_cursor[NN];
__device__ int   g_srcA[EE];
__device__ int   g_bsum[128];
__device__ float g_stat[2 * HH];       // [0:128) sum, [128:256) sumsq
__device__ float g_meanL[3 * HH];      // per-layer BN stats
__device__ float g_istdL[3 * HH];
__device__ int   g_goff[GG + 1];
__device__ float g_pool[GG * LH];
__device__ float g_z[GG * HH];
__device__ float g_m2[HH];
__device__ float g_i2[HH];

// ---------------- setup kernels ----------------
__global__ void k_count(const int* __restrict__ dst) {
    int e = blockIdx.x * blockDim.x + threadIdx.x;
    if (e < EE) atomicAdd(&g_cnt[dst[e]], 1);
}

// block-local exclusive scan + block sums; also writes dinv
__global__ void s_partial() {
    __shared__ int wsum[32];
    int tid = threadIdx.x, lane = tid & 31, wid = tid >> 5;
    int idx = blockIdx.x * 1024 + tid;
    int v = (idx < NN) ? g_cnt[idx] : 0;
    if (idx < NN) g_dinv[idx] = rsqrtf((float)(v + 1));
    int x = v;
    #pragma unroll
    for (int o = 1; o < 32; o <<= 1) {
        int y = __shfl_up_sync(0xffffffffu, x, o);
        if (lane >= o) x += y;
    }
    if (lane == 31) wsum[wid] = x;
    __syncthreads();
    if (wid == 0) {
        int w = wsum[lane];
        int xx = w;
        #pragma unroll
        for (int o = 1; o < 32; o <<= 1) {
            int y = __shfl_up_sync(0xffffffffu, xx, o);
            if (lane >= o) xx += y;
        }
        wsum[lane] = xx - w;
    }
    __syncthreads();
    int incl = x + wsum[wid];
    if (idx < NN) g_off[idx] = incl - v;     // block-local exclusive
    if (tid == 1023) g_bsum[blockIdx.x] = incl;
}

// finalize offsets, init cursor, zero g_cnt, graph offsets via boundary scan
__global__ void s_add(const int* __restrict__ batch) {
    __shared__ int sb[128];
    int tid = threadIdx.x;
    if (tid < 128) sb[tid] = (tid < NBLK) ? g_bsum[tid] : 0;
    __syncthreads();
    #pragma unroll
    for (int o = 1; o < 128; o <<= 1) {
        int v = 0;
        if (tid < 128 && tid >= o) v = sb[tid - o];
        __syncthreads();
        if (tid < 128) sb[tid] += v;
        __syncthreads();
    }
    int bpre = (blockIdx.x > 0) ? sb[blockIdx.x - 1] : 0;
    int idx = blockIdx.x * 1024 + tid;
    if (idx < NN) {
        int off = g_off[idx] + bpre;
        g_off[idx] = off;
        g_cursor[idx] = off;
        g_cnt[idx] = 0;                      // restore zero-invariant
        int b = batch[idx];
        int prev = (idx > 0) ? batch[idx - 1] : -1;
        for (int g = prev + 1; g <= b; g++) g_goff[g] = idx;
        if (idx == NN - 1)
            for (int g = b + 1; g <= GG; g++) g_goff[g] = NN;
    }
    if (idx == 0) g_off[NN] = EE;
}

__global__ void k_fill(const int* __restrict__ src, const int* __restrict__ dst) {
    int e = blockIdx.x * blockDim.x + threadIdx.x;
    if (e < EE) {
        int d = dst[e];
        int p = atomicAdd(&g_cursor[d], 1);
        g_srcA[p] = src[e];
    }
}

// ---------------- fp16 tensor-core GEMM (m16n8k16, fp32 accumulate) ----------------
__device__ __forceinline__ void mma_f16(float& c0, float& c1, float& c2, float& c3,
                                        uint32_t a0, uint32_t a1, uint32_t a2, uint32_t a3,
                                        uint32_t b0, uint32_t b1) {
    asm volatile("mma.sync.aligned.m16n8k16.row.col.f32.f16.f16.f32 "
                 "{%0,%1,%2,%3},{%4,%5,%6,%7},{%8,%9},{%0,%1,%2,%3};"
                 : "+f"(c0), "+f"(c1), "+f"(c2), "+f"(c3)
                 : "r"(a0), "r"(a1), "r"(a2), "r"(a3), "r"(b0), "r"(b1));
}

// generic 4-element load -> float4
__device__ __forceinline__ float4 load4(const float* p) { return *(const float4*)p; }
__device__ __forceinline__ float4 load4(const __half* p) {
    uint2 u = *(const uint2*)p;
    float2 lo = __half22float2(*(const __half2*)&u.x);
    float2 hi = __half22float2(*(const __half2*)&u.y);
    return make_float4(lo.x, lo.y, hi.x, hi.y);
}

#define BPAD 136  // sB row stride in halves (68 words): frag banks distinct
#define APAD 40   // sA row stride in halves (20 words): frag banks distinct

// C16[N,128] = fp16( dinv[row] * (relu(BN_layer(A))[N,128] @ W[128,128]) )
// W staged fully in smem once (fp16, transposed); A staged in 4 chunks of k=32.
template <typename TA>
__global__ __launch_bounds__(256, 2) void k_gemm_h(const TA* __restrict__ A,
                                                   const float* __restrict__ W,
                                                   __half* __restrict__ C16,
                                                   int doBN, int statLayer,
                                                   const float* __restrict__ gamma,
                                                   const float* __restrict__ beta) {
    __shared__ __align__(16) __half sB[128][BPAD];  // [n][k], full W transposed
    __shared__ __align__(16) __half sA[128][APAD];  // [row][k-chunk of 32]
    __shared__ float sScale[HH], sShift[HH];

    int tid = threadIdx.x;
    if (doBN && tid < HH) {
        float is = g_istdL[statLayer * HH + tid] * gamma[tid];
        sScale[tid] = is;
        sShift[tid] = beta[tid] - g_meanL[statLayer * HH + tid] * is;
    }

    // stage full W -> sB[n][k] fp16 (coalesced scalar global loads along n)
    #pragma unroll
    for (int i = 0; i < 16; i++) {
        int idx = i * 256 + tid;          // 4096 packs of 4 k-values
        int n  = idx & 127;
        int k0 = (idx >> 7) * 4;          // 0..124
        float w0 = W[(size_t)k0       * HH + n];
        float w1 = W[(size_t)(k0 + 1) * HH + n];
        float w2 = W[(size_t)(k0 + 2) * HH + n];
        float w3 = W[(size_t)(k0 + 3) * HH + n];
        __half2 h01 = __floats2half2_rn(w0, w1);
        __half2 h23 = __floats2half2_rn(w2, w3);
        uint2 pk = make_uint2(*(uint32_t*)&h01, *(uint32_t*)&h23);
        *(uint2*)&sB[n][k0] = pk;
    }
    __syncthreads();   // REQUIRED: orders sScale/sShift writes before A-staging reads

    int lane = tid & 31, wid = tid >> 5;
    int gid = lane >> 2, tig = lane & 3;
    int warp_m = wid & 3, warp_n = wid >> 2;     // 4 x 2 warp grid
    int mrow = warp_m * 32;
    int ncol0 = warp_n * 64;
    int rowBase = blockIdx.x * 128;

    float acc[2][8][4];
    #pragma unroll
    for (int mt = 0; mt < 2; mt++)
        #pragma unroll
        for (int nt = 0; nt < 8; nt++)
            #pragma unroll
            for (int r = 0; r < 4; r++) acc[mt][nt][r] = 0.f;

    for (int kc = 0; kc < 4; kc++) {
        int gcol = kc * 32;
        // stage A chunk [128 rows x 32 k] (BN+ReLU fused), fp16
        #pragma unroll
        for (int i = 0; i < 4; i++) {
            int v = i * 256 + tid;        // 1024 packs of 4
            int row = v & 127;
            int k0 = (v >> 7) * 4;        // 0..28
            int gr = rowBase + row;
            float4 a4 = make_float4(0.f, 0.f, 0.f, 0.f);
            if (gr < NN) a4 = load4(A + (size_t)gr * HH + gcol + k0);
            if (doBN) {
                int cb = gcol + k0;
                a4.x = fmaxf(0.f, fmaf(a4.x, sScale[cb], sShift[cb]));
                a4.y = fmaxf(0.f, fmaf(a4.y, sScale[cb + 1], sShift[cb + 1]));
                a4.z = fmaxf(0.f, fmaf(a4.z, sScale[cb + 2], sShift[cb + 2]));
                a4.w = fmaxf(0.f, fmaf(a4.w, sScale[cb + 3], sShift[cb + 3]));
            }
            __half2 h01 = __floats2half2_rn(a4.x, a4.y);
            __half2 h23 = __floats2half2_rn(a4.z, a4.w);
            uint2 pk = make_uint2(*(uint32_t*)&h01, *(uint32_t*)&h23);
            *(uint2*)&sA[row][k0] = pk;
        }
        __syncthreads();

        #pragma unroll
        for (int ks = 0; ks < 2; ks++) {
            int kb = ks * 16;                 // within chunk
            int kg = gcol + kb;               // global k for sB
            uint32_t a[2][4];
            #pragma unroll
            for (int mt = 0; mt < 2; mt++) {
                int m0 = mrow + mt * 16 + gid;
                a[mt][0] = *(const uint32_t*)&sA[m0][kb + 2 * tig];
                a[mt][1] = *(const uint32_t*)&sA[m0 + 8][kb + 2 * tig];
                a[mt][2] = *(const uint32_t*)&sA[m0][kb + 2 * tig + 8];
                a[mt][3] = *(const uint32_t*)&sA[m0 + 8][kb + 2 * tig + 8];
            }
            #pragma unroll
            for (int nt = 0; nt < 8; nt++) {
                int nc = ncol0 + nt * 8 + gid;
                uint32_t b0 = *(const uint32_t*)&sB[nc][kg + 2 * tig];
                uint32_t b1 = *(const uint32_t*)&sB[nc][kg + 2 * tig + 8];
                #pragma unroll
                for (int mt = 0; mt < 2; mt++) {
                    float* c = acc[mt][nt];
                    mma_f16(c[0], c[1], c[2], c[3],
                            a[mt][0], a[mt][1], a[mt][2], a[mt][3], b0, b1);
                }
            }
        }
        __syncthreads();
    }

    // epilogue: scale by dinv[row], convert fp16, write
    #pragma unroll
    for (int mt = 0; mt < 2; mt++) {
        int r0 = rowBase + mrow + mt * 16 + gid;
        int r1 = r0 + 8;
        float dv0 = (r0 < NN) ? g_dinv[r0] : 0.f;
        float dv1 = (r1 < NN) ? g_dinv[r1] : 0.f;
        #pragma unroll
        for (int nt = 0; nt < 8; nt++) {
            int c = ncol0 + nt * 8 + 2 * tig;
            float* a2 = acc[mt][nt];
            if (r0 < NN) *(__half2*)(C16 + (size_t)r0 * HH + c) = __floats2half2_rn(a2[0] * dv0, a2[1] * dv0);
            if (r1 < NN) *(__half2*)(C16 + (size_t)r1 * HH + c) = __floats2half2_rn(a2[2] * dv1, a2[3] * dv1);
        }
    }
}

// ---------------- aggregation: software-pipelined CSR gather + BN stats ----------------
// out[d] = dinv[d] * ( sum_{s in N(d)} hs[s] + hs[d] ),  hs = g_hW16 (dinv-scaled fp16)
#define AGG_GATHER(dst4, sidx) \
    { uint2 _r = *(const uint2*)(hw + (size_t)(sidx) * HH + col); dst4 = _r; }
#define AGG_ACC(r) \
    { float2 _a = __half22float2(*(__half2*)&(r).x); \
      float2 _b = __half22float2(*(__half2*)&(r).y); \
      ax += _a.x; ay += _a.y; az += _b.x; aw += _b.y; }

__global__ __launch_bounds__(256) void k_agg(const __half* __restrict__ hw,
                                             __half* __restrict__ out) {
    __shared__ float s_sum[HH], s_sq[HH];
    int tid = threadIdx.x;
    if (tid < HH) { s_sum[tid] = 0.f; s_sq[tid] = 0.f; }
    __syncthreads();
    int lane = tid & 31;
    int col = lane * 4;   // 4 halves (= 1 uint2) per lane, 32 lanes = 128 cols
    int gw = (blockIdx.x * blockDim.x + tid) >> 5;
    int nw = (gridDim.x * blockDim.x) >> 5;
    float lsx = 0.f, lsy = 0.f, lsz = 0.f, lsw = 0.f;
    float lqx = 0.f, lqy = 0.f, lqz = 0.f, lqw = 0.f;
    for (int node = gw; node < NN; node += nw) {
        uint2 rv;
        AGG_GATHER(rv, node);
        float2 f0 = __half22float2(*(__half2*)&rv.x);
        float2 f1 = __half22float2(*(__half2*)&rv.y);
        float ax = f0.x, ay = f0.y, az = f1.x, aw = f1.y;
        int e0 = __ldg(&g_off[node]), e1 = __ldg(&g_off[node + 1]);
        int deg = e1 - e0;
        int nf = deg >> 2;             // number of full 4-edge groups
        if (nf >= 2) {
            int s0 = __ldg(&g_srcA[e0]),     s1 = __ldg(&g_srcA[e0 + 1]);
            int s2 = __ldg(&g_srcA[e0 + 2]), s3 = __ldg(&g_srcA[e0 + 3]);
            uint2 p0, p1, p2, p3;
            AGG_GATHER(p0, s0); AGG_GATHER(p1, s1); AGG_GATHER(p2, s2); AGG_GATHER(p3, s3);
            int t0 = __ldg(&g_srcA[e0 + 4]), t1 = __ldg(&g_srcA[e0 + 5]);
            int t2 = __ldg(&g_srcA[e0 + 6]), t3 = __ldg(&g_srcA[e0 + 7]);
            int e = e0 + 8;
            int iters = nf - 2;
            while (iters > 0) {
                uint2 q0, q1, q2, q3;
                AGG_GATHER(q0, t0); AGG_GATHER(q1, t1); AGG_GATHER(q2, t2); AGG_GATHER(q3, t3);
                t0 = __ldg(&g_srcA[e]);     t1 = __ldg(&g_srcA[e + 1]);
                t2 = __ldg(&g_srcA[e + 2]); t3 = __ldg(&g_srcA[e + 3]);
                AGG_ACC(p0); AGG_ACC(p1); AGG_ACC(p2); AGG_ACC(p3);
                p0 = q0; p1 = q1; p2 = q2; p3 = q3;
                e += 4; iters--;
            }
            uint2 q0, q1, q2, q3;
            AGG_GATHER(q0, t0); AGG_GATHER(q1, t1); AGG_GATHER(q2, t2); AGG_GATHER(q3, t3);
            AGG_ACC(p0); AGG_ACC(p1); AGG_ACC(p2); AGG_ACC(p3);
            AGG_ACC(q0); AGG_ACC(q1); AGG_ACC(q2); AGG_ACC(q3);
        } else if (nf == 1) {
            int s0 = __ldg(&g_srcA[e0]),     s1 = __ldg(&g_srcA[e0 + 1]);
            int s2 = __ldg(&g_srcA[e0 + 2]), s3 = __ldg(&g_srcA[e0 + 3]);
            uint2 p0, p1, p2, p3;
            AGG_GATHER(p0, s0); AGG_GATHER(p1, s1); AGG_GATHER(p2, s2); AGG_GATHER(p3, s3);
            AGG_ACC(p0); AGG_ACC(p1); AGG_ACC(p2); AGG_ACC(p3);
        }
        for (int e = e0 + (nf << 2); e < e1; e++) {
            int s0 = __ldg(&g_srcA[e]);
            uint2 r0;
            AGG_GATHER(r0, s0);
            AGG_ACC(r0);
        }
        float dv = g_dinv[node];
        ax *= dv; ay *= dv; az *= dv; aw *= dv;
        __half2 o01 = __floats2half2_rn(ax, ay);
        __half2 o23 = __floats2half2_rn(az, aw);
        uint2 ov = make_uint2(*(uint32_t*)&o01, *(uint32_t*)&o23);
        *(uint2*)(out + (size_t)node * HH + col) = ov;
        lsx += ax; lsy += ay; lsz += az; lsw += aw;
        lqx += ax * ax; lqy += ay * ay; lqz += az * az; lqw += aw * aw;
    }
    atomicAdd(&s_sum[col], lsx);     atomicAdd(&s_sum[col + 1], lsy);
    atomicAdd(&s_sum[col + 2], lsz); atomicAdd(&s_sum[col + 3], lsw);
    atomicAdd(&s_sq[col], lqx);      atomicAdd(&s_sq[col + 1], lqy);
    atomicAdd(&s_sq[col + 2], lqz);  atomicAdd(&s_sq[col + 3], lqw);
    __syncthreads();
    if (tid < HH) {
        atomicAdd(&g_stat[tid], s_sum[tid]);
        atomicAdd(&g_stat[HH + tid], s_sq[tid]);
    }
}

__global__ void k_fin(int layer) {  // finalize layer BN stats, re-zero g_stat
    int t = threadIdx.x;
    if (t < HH) {
        float m = g_stat[t] * (1.f / NN);
        float v = g_stat[HH + t] * (1.f / NN) - m * m;
        g_meanL[layer * HH + t] = m;
        g_istdL[layer * HH + t] = rsqrtf(v + EPSV);
        g_stat[t] = 0.f;
        g_stat[HH + t] = 0.f;
    }
}

// per-graph mean pool with fused BN+ReLU (fp16 activations)
__global__ void k_pool(const __half* __restrict__ agg,
                       const float* __restrict__ gamma,
                       const float* __restrict__ beta, int layer) {
    int g = blockIdx.x, c = threadIdx.x;
    int b = g_goff[g], e = g_goff[g + 1];
    float is = g_istdL[layer * HH + c] * gamma[c];
    float sh = beta[c] - g_meanL[layer * HH + c] * is;
    float s = 0.f;
    for (int r = b; r < e; r++) {
        float x = __half2float(agg[(size_t)r * HH + c]);
        s += fmaxf(0.f, fmaf(x, is, sh));
    }
    int n = e - b;
    float cnt = (float)(n > 1 ? n : 1);
    g_pool[g * LH + layer * HH + c] = s / cnt;
}

// ---------------- MLP head ----------------
__global__ void k_lin1(const float* __restrict__ Wl1, const float* __restrict__ bl1) {
    __shared__ float sp[LH];
    int g = blockIdx.x, t = threadIdx.x;
    sp[t]       = g_pool[g * LH + t];
    sp[t + 128] = g_pool[g * LH + t + 128];
    sp[t + 256] = g_pool[g * LH + t + 256];
    __syncthreads();
    float a = bl1[t];
    #pragma unroll 4
    for (int k = 0; k < LH; k++) a = fmaf(sp[k], Wl1[k * HH + t], a);
    g_z[g * HH + t] = a;
}

__global__ void k_bn2() {
    int t = threadIdx.x;
    if (t < HH) {
        float s = 0.f, q = 0.f;
        for (int r = 0; r < GG; r++) {
            float x = g_z[r * HH + t];
            s += x; q += x * x;
        }
        float m = s * (1.f / GG);
        float v = q * (1.f / GG) - m * m;
        g_m2[t] = m;
        g_i2[t] = rsqrtf(v + EPSV);
    }
}

__global__ void k_final(const float* __restrict__ gl, const float* __restrict__ btl,
                        const float* __restrict__ Wl2, const float* __restrict__ bl2,
                        float* __restrict__ out) {
    __shared__ float zr[HH];
    __shared__ float lg[CC];
    __shared__ float s_ls;
    int g = blockIdx.x, t = threadIdx.x;
    float x = g_z[g * HH + t];
    zr[t] = fmaxf(0.f, (x - g_m2[t]) * g_i2[t] * gl[t] + btl[t]);
    __syncthreads();
    if (t < CC) {
        float d = bl2[t];
        #pragma unroll 4
        for (int j = 0; j < HH; j++) d = fmaf(zr[j], Wl2[j * CC + t], d);
        lg[t] = d;
    }
    __syncthreads();
    if (t == 0) {
        float m = lg[0];
        for (int c = 1; c < CC; c++) m = fmaxf(m, lg[c]);
        float se = 0.f;
        for (int c = 0; c < CC; c++) se += expf(lg[c] - m);
        s_ls = m + logf(se);
    }
    __syncthreads();
    if (t < CC) out[g * CC + t] = lg[t] - s_ls;
}

// ---------------- launch (single serial stream) ----------------
extern "C" void kernel_launch(void* const* d_in, const int* in_sizes, int n_in,
                              void* d_out, int out_size) {
    const float* x     = (const float*)d_in[0];
    const int*   ei    = (const int*)d_in[1];     // int32 (JAX x64 disabled)
    const int*   batch = (const int*)d_in[2];
    const float* W1  = (const float*)d_in[3];
    const float* g1  = (const float*)d_in[5];
    const float* bt1 = (const float*)d_in[6];
    const float* Wc  = (const float*)d_in[7];
    const float* gc  = (const float*)d_in[9];
    const float* btc = (const float*)d_in[10];
    const float* Wl1 = (const float*)d_in[11];
    const float* bl1 = (const float*)d_in[12];
    const float* gl  = (const float*)d_in[13];
    const float* btl = (const float*)d_in[14];
    const float* Wl2 = (const float*)d_in[15];
    const float* bl2 = (const float*)d_in[16];
    const int* src = ei;
    const int* dst = ei + EE;

    void *p_hW, *p_aggA, *p_aggB;
    cudaGetSymbolAddress(&p_hW, g_hW16);
    cudaGetSymbolAddress(&p_aggA, g_aggA);
    cudaGetSymbolAddress(&p_aggB, g_aggB);
    __half* hW   = (__half*)p_hW;
    __half* aggA = (__half*)p_aggA;
    __half* aggB = (__half*)p_aggB;

    const int GEMM_GRID = (NN + 127) / 128;
    const int AGG_GRID  = 1480;

    // ---- setup; kernel #4 (profiled) is k_gemm_h ----
    k_count<<<(EE + 255) / 256, 256>>>(dst);          // 1
    s_partial<<<NBLK, 1024>>>();                      // 2 (writes dinv)
    s_add<<<NBLK, 1024>>>(batch);                     // 3
    k_gemm_h<float><<<GEMM_GRID, 256>>>(x, W1, hW, 0, 0, (const float*)0, (const float*)0); // 4 (profiled)
    k_fill<<<(EE + 255) / 256, 256>>>(src, dst);      // 5

    // ---- layer 0 ----
    k_agg<<<AGG_GRID, 256>>>(hW, aggA);
    k_fin<<<1, 128>>>(0);
    k_pool<<<GG, 128>>>(aggA, g1, bt1, 0);

    // ---- layer 1: BN0(aggA) -> aggB ----
    k_gemm_h<__half><<<GEMM_GRID, 256>>>(aggA, Wc, hW, 1, 0, g1, bt1);
    k_agg<<<AGG_GRID, 256>>>(hW, aggB);
    k_fin<<<1, 128>>>(1);
    k_pool<<<GG, 128>>>(aggB, gc, btc, 1);

    // ---- layer 2: BN1(aggB) -> aggA ----
    k_gemm_h<__half><<<GEMM_GRID, 256>>>(aggB, Wc + HH * HH, hW, 1, 1, gc, btc);
    k_agg<<<AGG_GRID, 256>>>(hW, aggA);
    k_fin<<<1, 128>>>(2);
    k_pool<<<GG, 128>>>(aggA, gc + HH, btc + HH, 2);

    // ---- head ----
    k_lin1<<<GG, 128>>>(Wl1, bl1);
    k_bn2<<<1, 128>>>();
    k_final<<<GG, 128>>>(gl, btl, Wl2, bl2, (float*)d_out);
}

// round 13
// speedup vs baseline: 1.7408x; 1.0255x over previous
#include <cuda_runtime.h>
#include <cuda_fp16.h>
#include <cstdint>

#define NN 100000
#define EE 1600000
#define HH 128
#define GG 512
#define CC 10
#define LH 384   // L*H
#define EPSV 1e-5f
#define NBLK 98  // ceil(NN/1024)

// ---------------- device scratch (no allocations allowed) ----------------
// zero-invariants: g_cnt, g_stat are zero at entry of every call
__device__ __align__(16) __half g_hW16[NN * HH]; // GEMM output, fp16 (dinv-scaled)
__device__ __align__(16) __half g_aggA[NN * HH]; // aggregation ping (fp16)
__device__ __align__(16) __half g_aggB[NN * HH]; // aggregation pong (fp16)
__device__ float g_dinv[NN];
__device__ int   g_cnt[NN];
__device__ int   g_off[NN + 1];
__device__ int   g_cursor[NN];
__device__ int   g_srcA[EE];
__device__ int   g_bsum[128];
__device__ float g_stat[2 * HH];       // [0:128) sum, [128:256) sumsq
__device__ float g_meanL[3 * HH];      // per-layer BN stats
__device__ float g_istdL[3 * HH];
__device__ int   g_goff[GG + 1];
__device__ float g_pool[GG * LH];
__device__ float g_z[GG * HH];
__device__ float g_m2[HH];
__device__ float g_i2[HH];

// ---------------- setup kernels ----------------
__global__ void k_count(const int* __restrict__ dst) {
    int e = blockIdx.x * blockDim.x + threadIdx.x;
    if (e < EE) atomicAdd(&g_cnt[dst[e]], 1);
}

// block-local exclusive scan + block sums; also writes dinv
__global__ void s_partial() {
    __shared__ int wsum[32];
    int tid = threadIdx.x, lane = tid & 31, wid = tid >> 5;
    int idx = blockIdx.x * 1024 + tid;
    int v = (idx < NN) ? g_cnt[idx] : 0;
    if (idx < NN) g_dinv[idx] = rsqrtf((float)(v + 1));
    int x = v;
    #pragma unroll
    for (int o = 1; o < 32; o <<= 1) {
        int y = __shfl_up_sync(0xffffffffu, x, o);
        if (lane >= o) x += y;
    }
    if (lane == 31) wsum[wid] = x;
    __syncthreads();
    if (wid == 0) {
        int w = wsum[lane];
        int xx = w;
        #pragma unroll
        for (int o = 1; o < 32; o <<= 1) {
            int y = __shfl_up_sync(0xffffffffu, xx, o);
            if (lane >= o) xx += y;
        }
        wsum[lane] = xx - w;
    }
    __syncthreads();
    int incl = x + wsum[wid];
    if (idx < NN) g_off[idx] = incl - v;     // block-local exclusive
    if (tid == 1023) g_bsum[blockIdx.x] = incl;
}

// finalize offsets, init cursor, zero g_cnt, graph offsets via boundary scan
__global__ void s_add(const int* __restrict__ batch) {
    __shared__ int sb[128];
    int tid = threadIdx.x;
    if (tid < 128) sb[tid] = (tid < NBLK) ? g_bsum[tid] : 0;
    __syncthreads();
    #pragma unroll
    for (int o = 1; o < 128; o <<= 1) {
        int v = 0;
        if (tid < 128 && tid >= o) v = sb[tid - o];
        __syncthreads();
        if (tid < 128) sb[tid] += v;
        __syncthreads();
    }
    int bpre = (blockIdx.x > 0) ? sb[blockIdx.x - 1] : 0;
    int idx = blockIdx.x * 1024 + tid;
    if (idx < NN) {
        int off = g_off[idx] + bpre;
        g_off[idx] = off;
        g_cursor[idx] = off;
        g_cnt[idx] = 0;                      // restore zero-invariant
        int b = batch[idx];
        int prev = (idx > 0) ? batch[idx - 1] : -1;
        for (int g = prev + 1; g <= b; g++) g_goff[g] = idx;
        if (idx == NN - 1)
            for (int g = b + 1; g <= GG; g++) g_goff[g] = NN;
    }
    if (idx == 0) g_off[NN] = EE;
}

__global__ void k_fill(const int* __restrict__ src, const int* __restrict__ dst) {
    int e = blockIdx.x * blockDim.x + threadIdx.x;
    if (e < EE) {
        int d = dst[e];
        int p = atomicAdd(&g_cursor[d], 1);
        g_srcA[p] = src[e];
    }
}

// ---------------- fp16 tensor-core GEMM (m16n8k16, fp32 accumulate) ----------------
__device__ __forceinline__ void mma_f16(float& c0, float& c1, float& c2, float& c3,
                                        uint32_t a0, uint32_t a1, uint32_t a2, uint32_t a3,
                                        uint32_t b0, uint32_t b1) {
    asm volatile("mma.sync.aligned.m16n8k16.row.col.f32.f16.f16.f32 "
                 "{%0,%1,%2,%3},{%4,%5,%6,%7},{%8,%9},{%0,%1,%2,%3};"
                 : "+f"(c0), "+f"(c1), "+f"(c2), "+f"(c3)
                 : "r"(a0), "r"(a1), "r"(a2), "r"(a3), "r"(b0), "r"(b1));
}

// generic 4-element load -> float4
__device__ __forceinline__ float4 load4(const float* p) { return *(const float4*)p; }
__device__ __forceinline__ float4 load4(const __half* p) {
    uint2 u = *(const uint2*)p;
    float2 lo = __half22float2(*(const __half2*)&u.x);
    float2 hi = __half22float2(*(const __half2*)&u.y);
    return make_float4(lo.x, lo.y, hi.x, hi.y);
}

#define SPAD 136  // smem row stride in halves (68 words): frag banks 4*gid+tig, conflict-free
#define SMEM_SB_BYTES (128 * SPAD * 2)              // 34816
#define SMEM_SA_OFF   SMEM_SB_BYTES
#define SMEM_SC_OFF   (2 * SMEM_SB_BYTES)           // 69632
#define SMEM_GEMM     (SMEM_SC_OFF + 1024)          // 70656 total dynamic smem

// C16[N,128] = fp16( dinv[row] * (relu(BN_layer(A))[N,128] @ W[128,128]) )
// Full W AND full A tile staged in dynamic smem; 2 syncs per CTA, 8 k-step MMA block.
template <typename TA>
__global__ __launch_bounds__(256, 2) void k_gemm_h(const TA* __restrict__ A,
                                                   const float* __restrict__ W,
                                                   __half* __restrict__ C16,
                                                   int doBN, int statLayer,
                                                   const float* __restrict__ gamma,
                                                   const float* __restrict__ beta) {
    extern __shared__ __align__(16) char smem[];
    __half (*sB)[SPAD] = (__half(*)[SPAD])(smem);                 // [n][k], W transposed
    __half (*sA)[SPAD] = (__half(*)[SPAD])(smem + SMEM_SA_OFF);   // [row][k]
    float* sScale = (float*)(smem + SMEM_SC_OFF);
    float* sShift = sScale + HH;

    int tid = threadIdx.x;
    if (doBN && tid < HH) {
        float is = g_istdL[statLayer * HH + tid] * gamma[tid];
        sScale[tid] = is;
        sShift[tid] = beta[tid] - g_meanL[statLayer * HH + tid] * is;
    }

    // stage full W -> sB[n][k] fp16 (coalesced scalar global loads along n)
    #pragma unroll
    for (int i = 0; i < 16; i++) {
        int idx = i * 256 + tid;          // 4096 packs of 4 k-values
        int n  = idx & 127;
        int k0 = (idx >> 7) * 4;          // 0..124
        float w0 = W[(size_t)k0       * HH + n];
        float w1 = W[(size_t)(k0 + 1) * HH + n];
        float w2 = W[(size_t)(k0 + 2) * HH + n];
        float w3 = W[(size_t)(k0 + 3) * HH + n];
        __half2 h01 = __floats2half2_rn(w0, w1);
        __half2 h23 = __floats2half2_rn(w2, w3);
        uint2 pk = make_uint2(*(uint32_t*)&h01, *(uint32_t*)&h23);
        *(uint2*)&sB[n][k0] = pk;
    }
    __syncthreads();   // orders sScale/sShift writes before A-staging reads

    int rowBase = blockIdx.x * 128;

    // stage full A tile [128 x 128] (BN+ReLU fused), fp16 — 16 packs/thread, MLP-heavy
    #pragma unroll
    for (int i = 0; i < 16; i++) {
        int v = i * 256 + tid;
        int row = v & 127;
        int k0 = (v >> 7) * 4;            // 0..124
        int gr = rowBase + row;
        float4 a4 = make_float4(0.f, 0.f, 0.f, 0.f);
        if (gr < NN) a4 = load4(A + (size_t)gr * HH + k0);
        if (doBN) {
            a4.x = fmaxf(0.f, fmaf(a4.x, sScale[k0], sShift[k0]));
            a4.y = fmaxf(0.f, fmaf(a4.y, sScale[k0 + 1], sShift[k0 + 1]));
            a4.z = fmaxf(0.f, fmaf(a4.z, sScale[k0 + 2], sShift[k0 + 2]));
            a4.w = fmaxf(0.f, fmaf(a4.w, sScale[k0 + 3], sShift[k0 + 3]));
        }
        __half2 h01 = __floats2half2_rn(a4.x, a4.y);
        __half2 h23 = __floats2half2_rn(a4.z, a4.w);
        uint2 pk = make_uint2(*(uint32_t*)&h01, *(uint32_t*)&h23);
        *(uint2*)&sA[row][k0] = pk;
    }
    __syncthreads();

    int lane = tid & 31, wid = tid >> 5;
    int gid = lane >> 2, tig = lane & 3;
    int warp_m = wid & 3, warp_n = wid >> 2;     // 4 x 2 warp grid
    int mrow = warp_m * 32;
    int ncol0 = warp_n * 64;

    float acc[2][8][4];
    #pragma unroll
    for (int mt = 0; mt < 2; mt++)
        #pragma unroll
        for (int nt = 0; nt < 8; nt++)
            #pragma unroll
            for (int r = 0; r < 4; r++) acc[mt][nt][r] = 0.f;

    #pragma unroll
    for (int ks = 0; ks < 8; ks++) {
        int kg = ks * 16;
        uint32_t a[2][4];
        #pragma unroll
        for (int mt = 0; mt < 2; mt++) {
            int m0 = mrow + mt * 16 + gid;
            a[mt][0] = *(const uint32_t*)&sA[m0][kg + 2 * tig];
            a[mt][1] = *(const uint32_t*)&sA[m0 + 8][kg + 2 * tig];
            a[mt][2] = *(const uint32_t*)&sA[m0][kg + 2 * tig + 8];
            a[mt][3] = *(const uint32_t*)&sA[m0 + 8][kg + 2 * tig + 8];
        }
        #pragma unroll
        for (int nt = 0; nt < 8; nt++) {
            int nc = ncol0 + nt * 8 + gid;
            uint32_t b0 = *(const uint32_t*)&sB[nc][kg + 2 * tig];
            uint32_t b1 = *(const uint32_t*)&sB[nc][kg + 2 * tig + 8];
            #pragma unroll
            for (int mt = 0; mt < 2; mt++) {
                float* c = acc[mt][nt];
                mma_f16(c[0], c[1], c[2], c[3],
                        a[mt][0], a[mt][1], a[mt][2], a[mt][3], b0, b1);
            }
        }
    }

    // epilogue: scale by dinv[row], convert fp16, write
    #pragma unroll
    for (int mt = 0; mt < 2; mt++) {
        int r0 = rowBase + mrow + mt * 16 + gid;
        int r1 = r0 + 8;
        float dv0 = (r0 < NN) ? g_dinv[r0] : 0.f;
        float dv1 = (r1 < NN) ? g_dinv[r1] : 0.f;
        #pragma unroll
        for (int nt = 0; nt < 8; nt++) {
            int c = ncol0 + nt * 8 + 2 * tig;
            float* a2 = acc[mt][nt];
            if (r0 < NN) *(__half2*)(C16 + (size_t)r0 * HH + c) = __floats2half2_rn(a2[0] * dv0, a2[1] * dv0);
            if (r1 < NN) *(__half2*)(C16 + (size_t)r1 * HH + c) = __floats2half2_rn(a2[2] * dv1, a2[3] * dv1);
        }
    }
}

// ---------------- aggregation: software-pipelined CSR gather + BN stats ----------------
// out[d] = dinv[d] * ( sum_{s in N(d)} hs[s] + hs[d] ),  hs = g_hW16 (dinv-scaled fp16)
#define AGG_GATHER(dst4, sidx) \
    { uint2 _r = *(const uint2*)(hw + (size_t)(sidx) * HH + col); dst4 = _r; }
#define AGG_ACC(r) \
    { float2 _a = __half22float2(*(__half2*)&(r).x); \
      float2 _b = __half22float2(*(__half2*)&(r).y); \
      ax += _a.x; ay += _a.y; az += _b.x; aw += _b.y; }

__global__ __launch_bounds__(256) void k_agg(const __half* __restrict__ hw,
                                             __half* __restrict__ out) {
    __shared__ float s_sum[HH], s_sq[HH];
    int tid = threadIdx.x;
    if (tid < HH) { s_sum[tid] = 0.f; s_sq[tid] = 0.f; }
    __syncthreads();
    int lane = tid & 31;
    int col = lane * 4;   // 4 halves (= 1 uint2) per lane, 32 lanes = 128 cols
    int gw = (blockIdx.x * blockDim.x + tid) >> 5;
    int nw = (gridDim.x * blockDim.x) >> 5;
    float lsx = 0.f, lsy = 0.f, lsz = 0.f, lsw = 0.f;
    float lqx = 0.f, lqy = 0.f, lqz = 0.f, lqw = 0.f;
    for (int node = gw; node < NN; node += nw) {
        uint2 rv;
        AGG_GATHER(rv, node);
        float2 f0 = __half22float2(*(__half2*)&rv.x);
        float2 f1 = __half22float2(*(__half2*)&rv.y);
        float ax = f0.x, ay = f0.y, az = f1.x, aw = f1.y;
        int e0 = __ldg(&g_off[node]), e1 = __ldg(&g_off[node + 1]);
        int deg = e1 - e0;
        int nf = deg >> 2;             // number of full 4-edge groups
        if (nf >= 2) {
            int s0 = __ldg(&g_srcA[e0]),     s1 = __ldg(&g_srcA[e0 + 1]);
            int s2 = __ldg(&g_srcA[e0 + 2]), s3 = __ldg(&g_srcA[e0 + 3]);
            uint2 p0, p1, p2, p3;
            AGG_GATHER(p0, s0); AGG_GATHER(p1, s1); AGG_GATHER(p2, s2); AGG_GATHER(p3, s3);
            int t0 = __ldg(&g_srcA[e0 + 4]), t1 = __ldg(&g_srcA[e0 + 5]);
            int t2 = __ldg(&g_srcA[e0 + 6]), t3 = __ldg(&g_srcA[e0 + 7]);
            int e = e0 + 8;
            int iters = nf - 2;
            while (iters > 0) {
                uint2 q0, q1, q2, q3;
                AGG_GATHER(q0, t0); AGG_GATHER(q1, t1); AGG_GATHER(q2, t2); AGG_GATHER(q3, t3);
                t0 = __ldg(&g_srcA[e]);     t1 = __ldg(&g_srcA[e + 1]);
                t2 = __ldg(&g_srcA[e + 2]); t3 = __ldg(&g_srcA[e + 3]);
                AGG_ACC(p0); AGG_ACC(p1); AGG_ACC(p2); AGG_ACC(p3);
                p0 = q0; p1 = q1; p2 = q2; p3 = q3;
                e += 4; iters--;
            }
            uint2 q0, q1, q2, q3;
            AGG_GATHER(q0, t0); AGG_GATHER(q1, t1); AGG_GATHER(q2, t2); AGG_GATHER(q3, t3);
            AGG_ACC(p0); AGG_ACC(p1); AGG_ACC(p2); AGG_ACC(p3);
            AGG_ACC(q0); AGG_ACC(q1); AGG_ACC(q2); AGG_ACC(q3);
        } else if (nf == 1) {
            int s0 = __ldg(&g_srcA[e0]),     s1 = __ldg(&g_srcA[e0 + 1]);
            int s2 = __ldg(&g_srcA[e0 + 2]), s3 = __ldg(&g_srcA[e0 + 3]);
            uint2 p0, p1, p2, p3;
            AGG_GATHER(p0, s0); AGG_GATHER(p1, s1); AGG_GATHER(p2, s2); AGG_GATHER(p3, s3);
            AGG_ACC(p0); AGG_ACC(p1); AGG_ACC(p2); AGG_ACC(p3);
        }
        for (int e = e0 + (nf << 2); e < e1; e++) {
            int s0 = __ldg(&g_srcA[e]);
            uint2 r0;
            AGG_GATHER(r0, s0);
            AGG_ACC(r0);
        }
        float dv = g_dinv[node];
        ax *= dv; ay *= dv; az *= dv; aw *= dv;
        __half2 o01 = __floats2half2_rn(ax, ay);
        __half2 o23 = __floats2half2_rn(az, aw);
        uint2 ov = make_uint2(*(uint32_t*)&o01, *(uint32_t*)&o23);
        *(uint2*)(out + (size_t)node * HH + col) = ov;
        lsx += ax; lsy += ay; lsz += az; lsw += aw;
        lqx += ax * ax; lqy += ay * ay; lqz += az * az; lqw += aw * aw;
    }
    atomicAdd(&s_sum[col], lsx);     atomicAdd(&s_sum[col + 1], lsy);
    atomicAdd(&s_sum[col + 2], lsz); atomicAdd(&s_sum[col + 3], lsw);
    atomicAdd(&s_sq[col], lqx);      atomicAdd(&s_sq[col + 1], lqy);
    atomicAdd(&s_sq[col + 2], lqz);  atomicAdd(&s_sq[col + 3], lqw);
    __syncthreads();
    if (tid < HH) {
        atomicAdd(&g_stat[tid], s_sum[tid]);
        atomicAdd(&g_stat[HH + tid], s_sq[tid]);
    }
}

__global__ void k_fin(int layer) {  // finalize layer BN stats, re-zero g_stat
    int t = threadIdx.x;
    if (t < HH) {
        float m = g_stat[t] * (1.f / NN);
        float v = g_stat[HH + t] * (1.f / NN) - m * m;
        g_meanL[layer * HH + t] = m;
        g_istdL[layer * HH + t] = rsqrtf(v + EPSV);
        g_stat[t] = 0.f;
        g_stat[HH + t] = 0.f;
    }
}

// per-graph mean pool with fused BN+ReLU (fp16 activations)
__global__ void k_pool(const __half* __restrict__ agg,
                       const float* __restrict__ gamma,
                       const float* __restrict__ beta, int layer) {
    int g = blockIdx.x, c = threadIdx.x;
    int b = g_goff[g], e = g_goff[g + 1];
    float is = g_istdL[layer * HH + c] * gamma[c];
    float sh = beta[c] - g_meanL[layer * HH + c] * is;
    float s = 0.f;
    for (int r = b; r < e; r++) {
        float x = __half2float(agg[(size_t)r * HH + c]);
        s += fmaxf(0.f, fmaf(x, is, sh));
    }
    int n = e - b;
    float cnt = (float)(n > 1 ? n : 1);
    g_pool[g * LH + layer * HH + c] = s / cnt;
}

// ---------------- MLP head ----------------
__global__ void k_lin1(const float* __restrict__ Wl1, const float* __restrict__ bl1) {
    __shared__ float sp[LH];
    int g = blockIdx.x, t = threadIdx.x;
    sp[t]       = g_pool[g * LH + t];
    sp[t + 128] = g_pool[g * LH + t + 128];
    sp[t + 256] = g_pool[g * LH + t + 256];
    __syncthreads();
    float a = bl1[t];
    #pragma unroll 4
    for (int k = 0; k < LH; k++) a = fmaf(sp[k], Wl1[k * HH + t], a);
    g_z[g * HH + t] = a;
}

__global__ void k_bn2() {
    int t = threadIdx.x;
    if (t < HH) {
        float s = 0.f, q = 0.f;
        for (int r = 0; r < GG; r++) {
            float x = g_z[r * HH + t];
            s += x; q += x * x;
        }
        float m = s * (1.f / GG);
        float v = q * (1.f / GG) - m * m;
        g_m2[t] = m;
        g_i2[t] = rsqrtf(v + EPSV);
    }
}

__global__ void k_final(const float* __restrict__ gl, const float* __restrict__ btl,
                        const float* __restrict__ Wl2, const float* __restrict__ bl2,
                        float* __restrict__ out) {
    __shared__ float zr[HH];
    __shared__ float lg[CC];
    __shared__ float s_ls;
    int g = blockIdx.x, t = threadIdx.x;
    float x = g_z[g * HH + t];
    zr[t] = fmaxf(0.f, (x - g_m2[t]) * g_i2[t] * gl[t] + btl[t]);
    __syncthreads();
    if (t < CC) {
        float d = bl2[t];
        #pragma unroll 4
        for (int j = 0; j < HH; j++) d = fmaf(zr[j], Wl2[j * CC + t], d);
        lg[t] = d;
    }
    __syncthreads();
    if (t == 0) {
        float m = lg[0];
        for (int c = 1; c < CC; c++) m = fmaxf(m, lg[c]);
        float se = 0.f;
        for (int c = 0; c < CC; c++) se += expf(lg[c] - m);
        s_ls = m + logf(se);
    }
    __syncthreads();
    if (t < CC) out[g * CC + t] = lg[t] - s_ls;
}

// ---------------- launch (single serial stream) ----------------
extern "C" void kernel_launch(void* const* d_in, const int* in_sizes, int n_in,
                              void* d_out, int out_size) {
    const float* x     = (const float*)d_in[0];
    const int*   ei    = (const int*)d_in[1];     // int32 (JAX x64 disabled)
    const int*   batch = (const int*)d_in[2];
    const float* W1  = (const float*)d_in[3];
    const float* g1  = (const float*)d_in[5];
    const float* bt1 = (const float*)d_in[6];
    const float* Wc  = (const float*)d_in[7];
    const float* gc  = (const float*)d_in[9];
    const float* btc = (const float*)d_in[10];
    const float* Wl1 = (const float*)d_in[11];
    const float* bl1 = (const float*)d_in[12];
    const float* gl  = (const float*)d_in[13];
    const float* btl = (const float*)d_in[14];
    const float* Wl2 = (const float*)d_in[15];
    const float* bl2 = (const float*)d_in[16];
    const int* src = ei;
    const int* dst = ei + EE;

    void *p_hW, *p_aggA, *p_aggB;
    cudaGetSymbolAddress(&p_hW, g_hW16);
    cudaGetSymbolAddress(&p_aggA, g_aggA);
    cudaGetSymbolAddress(&p_aggB, g_aggB);
    __half* hW   = (__half*)p_hW;
    __half* aggA = (__half*)p_aggA;
    __half* aggB = (__half*)p_aggB;

    // allow 69KB dynamic smem for the GEMM (host attribute, idempotent, capture-safe)
    cudaFuncSetAttribute(k_gemm_h<float>,  cudaFuncAttributeMaxDynamicSharedMemorySize, SMEM_GEMM);
    cudaFuncSetAttribute(k_gemm_h<__half>, cudaFuncAttributeMaxDynamicSharedMemorySize, SMEM_GEMM);

    const int GEMM_GRID = (NN + 127) / 128;
    const int AGG_GRID  = 1480;

    // ---- setup; kernel #4 (profiled) is k_gemm_h ----
    k_count<<<(EE + 255) / 256, 256>>>(dst);          // 1
    s_partial<<<NBLK, 1024>>>();                      // 2 (writes dinv)
    s_add<<<NBLK, 1024>>>(batch);                     // 3
    k_gemm_h<float><<<GEMM_GRID, 256, SMEM_GEMM>>>(x, W1, hW, 0, 0, (const float*)0, (const float*)0); // 4 (profiled)
    k_fill<<<(EE + 255) / 256, 256>>>(src, dst);      // 5

    // ---- layer 0 ----
    k_agg<<<AGG_GRID, 256>>>(hW, aggA);
    k_fin<<<1, 128>>>(0);
    k_pool<<<GG, 128>>>(aggA, g1, bt1, 0);

    // ---- layer 1: BN0(aggA) -> aggB ----
    k_gemm_h<__half><<<GEMM_GRID, 256, SMEM_GEMM>>>(aggA, Wc, hW, 1, 0, g1, bt1);
    k_agg<<<AGG_GRID, 256>>>(hW, aggB);
    k_fin<<<1, 128>>>(1);
    k_pool<<<GG, 128>>>(aggB, gc, btc, 1);

    // ---- layer 2: BN1(aggB) -> aggA ----
    k_gemm_h<__half><<<GEMM_GRID, 256, SMEM_GEMM>>>(aggB, Wc + HH * HH, hW, 1, 1, gc, btc);
    k_agg<<<AGG_GRID, 256>>>(hW, aggA);
    k_fin<<<1, 128>>>(2);
    k_pool<<<GG, 128>>>(aggA, gc + HH, btc + HH, 2);

    // ---- head ----
    k_lin1<<<GG, 128>>>(Wl1, bl1);
    k_bn2<<<1, 128>>>();
    k_final<<<GG, 128>>>(gl, btl, Wl2, bl2, (float*)d_out);
}